// round 1
// baseline (speedup 1.0000x reference)
#include <cuda_runtime.h>
#include <math.h>
#include <stdint.h>

#define V     8192
#define NREF  262144
#define NALT  131072
#define FREAD 11
#define FINFO 9
#define H     256
#define MAX_ALT 10

#define TILE_R 128
#define HT_PITCH 130   // 128 rows + pad (even -> 8B aligned pairs, 130%32=2 -> <=2-way conflicts)

// ---------------- scratch (__device__ globals: no allocation allowed) ----------------
__device__ float g_ref_sums[V * H];     // 8 MB
__device__ float g_alt_sums[V * H];     // 8 MB
__device__ int   g_ref_cnt[V];
__device__ int   g_alt_cnt[V];
__device__ float g_X[V * 3 * H];        // 24 MB: [ref_mean | alt_mean | omega]

// ---------------- helpers ----------------
__device__ __forceinline__ float lrelu(float x) { return x > 0.f ? x : 0.01f * x; }
__device__ __forceinline__ float sigmoidf_(float x) { return 1.f / (1.f + __expf(-x)); }

__device__ __forceinline__ unsigned long long pack2(float lo, float hi) {
    unsigned long long r;
    asm("mov.b64 %0, {%1, %2};" : "=l"(r) : "f"(lo), "f"(hi));
    return r;
}
__device__ __forceinline__ void unpack2(unsigned long long v, float& lo, float& hi) {
    asm("mov.b64 {%0, %1}, %2;" : "=f"(lo), "=f"(hi) : "l"(v));
}
__device__ __forceinline__ void ffma2(unsigned long long& d, unsigned long long a, unsigned long long b) {
    asm("fma.rn.f32x2 %0, %1, %2, %0;" : "+l"(d) : "l"(a), "l"(b));
}

// ---------------- kernel 0: zero the accumulators (graph replays re-run this) ----------------
__global__ void zero_kernel() {
    int idx = blockIdx.x * blockDim.x + threadIdx.x;
    if (idx < V * H) { g_ref_sums[idx] = 0.f; g_alt_sums[idx] = 0.f; }
    if (idx < V)     { g_ref_cnt[idx] = 0;    g_alt_cnt[idx] = 0; }
}

// ---------------- kernel 1: fused phi MLP + sorted-segment reduction ----------------
// Block = 128 contiguous reads (NREF = 2048*128, so no block straddles ref/alt).
// smem: hsT[256][130] (transposed h, later y) | ws[64][256] W1 k-chunk | xs[128][12] | segs[128]
#define PHI_SMEM_FLOATS (H * HT_PITCH + 64 * H + TILE_R * 12)
#define PHI_SMEM_BYTES  (PHI_SMEM_FLOATS * 4 + TILE_R * 4)

__global__ __launch_bounds__(512, 1) void phi_kernel(
    const float* __restrict__ reads,
    const int* __restrict__ ref_seg, const int* __restrict__ alt_seg,
    const float* __restrict__ W0, const float* __restrict__ b0,
    const float* __restrict__ W1, const float* __restrict__ b1)
{
    extern __shared__ float smem[];
    float* hsT = smem;                          // H * HT_PITCH
    float* ws  = smem + H * HT_PITCH;           // 64 * H
    float* xs  = ws + 64 * H;                   // 128 * 12
    int*   segs = (int*)(xs + TILE_R * 12);     // 128

    const int tid = threadIdx.x;
    const long base = (long)blockIdx.x * TILE_R;
    const bool is_alt = (base >= NREF);
    const int* seg_src = is_alt ? (alt_seg + (base - NREF)) : (ref_seg + base);

    // load reads tile + segment ids
    for (int idx = tid; idx < TILE_R * FREAD; idx += 512) {
        int r = idx / FREAD, c = idx % FREAD;
        xs[r * 12 + c] = reads[(base + r) * FREAD + c];
    }
    if (tid < TILE_R) segs[tid] = seg_src[tid];
    __syncthreads();

    // ---- stage 1: h = lrelu(x @ W0 + b0), stored transposed hsT[j][r]
    {
        const int j  = tid & 255;
        const int r0 = (tid >> 8) * 64;
        float w[FREAD];
        #pragma unroll
        for (int k = 0; k < FREAD; k++) w[k] = W0[k * H + j];
        const float bb = b0[j];
        for (int r = r0; r < r0 + 64; r++) {
            float acc = bb;
            #pragma unroll
            for (int k = 0; k < FREAD; k++) acc = fmaf(xs[r * 12 + k], w[k], acc);
            hsT[j * HT_PITCH + r] = lrelu(acc);
        }
    }
    __syncthreads();

    // ---- stage 2: y = sigmoid(h @ W1 + b1), f32x2 register tiling
    // thread (tr = warp 0..15, tc = lane 0..31): row-pairs {2tr+32i, +1}, cols {tc+32j}
    const int tr = tid >> 5;
    const int tc = tid & 31;
    unsigned long long acc[4][8];
    #pragma unroll
    for (int i = 0; i < 4; i++)
        #pragma unroll
        for (int j = 0; j < 8; j++) acc[i][j] = 0ULL;

    for (int kb = 0; kb < 4; kb++) {
        for (int idx = tid; idx < 64 * H; idx += 512)
            ws[idx] = W1[kb * 64 * H + idx];     // ws[k][c]
        __syncthreads();
        #pragma unroll 2
        for (int k = 0; k < 64; k++) {
            const float* hrow = &hsT[(kb * 64 + k) * HT_PITCH];
            unsigned long long a[4];
            #pragma unroll
            for (int i = 0; i < 4; i++)
                a[i] = *(const unsigned long long*)(hrow + 32 * i + 2 * tr);
            const float* wrow = &ws[k * H];
            #pragma unroll
            for (int j = 0; j < 8; j++) {
                float b = wrow[tc + 32 * j];
                unsigned long long b2 = pack2(b, b);
                #pragma unroll
                for (int i = 0; i < 4; i++) ffma2(acc[i][j], a[i], b2);
            }
        }
        __syncthreads();   // also protects hsT overwrite below after last chunk
    }

    // bias + sigmoid, write y back transposed into hsT[c][r]
    float bias[8];
    #pragma unroll
    for (int j = 0; j < 8; j++) bias[j] = b1[tc + 32 * j];
    #pragma unroll
    for (int i = 0; i < 4; i++) {
        const int r = 2 * tr + 32 * i;
        #pragma unroll
        for (int j = 0; j < 8; j++) {
            float lo, hi;
            unpack2(acc[i][j], lo, hi);
            lo = sigmoidf_(lo + bias[j]);
            hi = sigmoidf_(hi + bias[j]);
            const int c = tc + 32 * j;
            hsT[c * HT_PITCH + r]     = lo;
            hsT[c * HT_PITCH + r + 1] = hi;
        }
    }
    __syncthreads();

    // ---- sorted-run segment reduction + few atomics
    float* sums = is_alt ? g_alt_sums : g_ref_sums;
    if (tid < H) {
        const int c = tid;
        int cur = segs[0];
        float a = 0.f;
        for (int r = 0; r < TILE_R; r++) {
            int s = segs[r];
            if (s != cur) { atomicAdd(&sums[cur * H + c], a); a = 0.f; cur = s; }
            a += hsT[c * HT_PITCH + r];
        }
        atomicAdd(&sums[cur * H + c], a);
    } else if (tid == H) {
        int* cnt = is_alt ? g_alt_cnt : g_ref_cnt;
        int cur = segs[0], n = 0;
        for (int r = 0; r < TILE_R; r++) {
            int s = segs[r];
            if (s != cur) { atomicAdd(&cnt[cur], n); n = 0; cur = s; }
            n++;
        }
        atomicAdd(&cnt[cur], n);
    }
}

// ---------------- kernel 2: build X = [ref_mean | alt_mean | sigmoid(info@omW0+omb0)] ----------------
__global__ __launch_bounds__(256) void build_X_kernel(
    const float* __restrict__ info,
    const float* __restrict__ omW0, const float* __restrict__ omb0)
{
    const int c = threadIdx.x;
    const int v0 = blockIdx.x * 8;
    float w[FINFO];
    #pragma unroll
    for (int k = 0; k < FINFO; k++) w[k] = omW0[k * H + c];
    const float bb = omb0[c];
    for (int vl = 0; vl < 8; vl++) {
        const int v = v0 + vl;
        const float rc = (float)max(g_ref_cnt[v], 1);
        const float ac = (float)max(g_alt_cnt[v], 1);
        g_X[v * 768 + c]           = g_ref_sums[v * H + c] / rc;
        g_X[v * 768 + 256 + c]     = g_alt_sums[v * H + c] / ac;
        float z = bb;
        #pragma unroll
        for (int k = 0; k < FINFO; k++) z = fmaf(__ldg(&info[v * FINFO + k]), w[k], z);
        g_X[v * 768 + 512 + c]     = sigmoidf_(z);
    }
}

// ---------------- kernel 3: rho MLP + per-type out heads + select/scale/tanh ----------------
// Block = 32 variants, 256 threads (tr=tid/64 rows tr+4i, tc=tid%64 cols tc+64j)
#define HEAD_SMEM_FLOATS (64 * H + 32 * 257 + 32 * 65 + 32)
#define HEAD_SMEM_BYTES  (HEAD_SMEM_FLOATS * 4)

__global__ __launch_bounds__(256, 2) void head_kernel(
    const int* __restrict__ vtypes,
    const float* __restrict__ rhoW0, const float* __restrict__ rhob0,
    const float* __restrict__ rhoW1, const float* __restrict__ rhob1,
    const float* __restrict__ outW1, const float* __restrict__ outb1,
    const float* __restrict__ outW2, const float* __restrict__ outb2,
    const float* __restrict__ conf,  const float* __restrict__ max_logit,
    float* __restrict__ out)
{
    extern __shared__ float smem[];
    float* ws       = smem;                   // 64*H
    float* z1s      = ws + 64 * H;            // 32*257
    float* xs       = z1s + 32 * 257;         // 32*65
    float* logits_s = xs + 32 * 65;           // 32

    const int tid = threadIdx.x;
    const int tr = tid >> 6;     // 0..3
    const int tc = tid & 63;     // 0..63
    const int v0 = blockIdx.x * 32;

    float acc[8][4];

    // ---- phase 1: z1 = lrelu(X @ rhoW0 + rhob0)   (K = 768)
    #pragma unroll
    for (int i = 0; i < 8; i++)
        #pragma unroll
        for (int j = 0; j < 4; j++) acc[i][j] = 0.f;

    for (int kb = 0; kb < 12; kb++) {
        for (int idx = tid; idx < 32 * 64; idx += 256) {
            int r = idx >> 6, k = idx & 63;
            xs[r * 65 + k] = g_X[(v0 + r) * 768 + kb * 64 + k];
        }
        for (int idx = tid; idx < 64 * H; idx += 256)
            ws[idx] = rhoW0[kb * 64 * H + idx];
        __syncthreads();
        for (int k = 0; k < 64; k++) {
            float a[8], b[4];
            #pragma unroll
            for (int i = 0; i < 8; i++) a[i] = xs[(tr + 4 * i) * 65 + k];
            #pragma unroll
            for (int j = 0; j < 4; j++) b[j] = ws[k * H + tc + 64 * j];
            #pragma unroll
            for (int i = 0; i < 8; i++)
                #pragma unroll
                for (int j = 0; j < 4; j++) acc[i][j] = fmaf(a[i], b[j], acc[i][j]);
        }
        __syncthreads();
    }
    #pragma unroll
    for (int j = 0; j < 4; j++) {
        const float bb = rhob0[tc + 64 * j];
        #pragma unroll
        for (int i = 0; i < 8; i++)
            z1s[(tr + 4 * i) * 257 + tc + 64 * j] = lrelu(acc[i][j] + bb);
    }
    __syncthreads();

    // ---- phase 2: agg = z1 @ rhoW1 + rhob1   (no activation)
    #pragma unroll
    for (int i = 0; i < 8; i++)
        #pragma unroll
        for (int j = 0; j < 4; j++) acc[i][j] = 0.f;

    for (int kb = 0; kb < 4; kb++) {
        for (int idx = tid; idx < 64 * H; idx += 256)
            ws[idx] = rhoW1[kb * 64 * H + idx];
        __syncthreads();
        for (int k = 0; k < 64; k++) {
            float a[8], b[4];
            #pragma unroll
            for (int i = 0; i < 8; i++) a[i] = z1s[(tr + 4 * i) * 257 + kb * 64 + k];
            #pragma unroll
            for (int j = 0; j < 4; j++) b[j] = ws[k * H + tc + 64 * j];
            #pragma unroll
            for (int i = 0; i < 8; i++)
                #pragma unroll
                for (int j = 0; j < 4; j++) acc[i][j] = fmaf(a[i], b[j], acc[i][j]);
        }
        __syncthreads();
    }
    // overwrite z1s with agg (all reads done at loop-end sync)
    #pragma unroll
    for (int j = 0; j < 4; j++) {
        const float bb = rhob1[tc + 64 * j];
        #pragma unroll
        for (int i = 0; i < 8; i++)
            z1s[(tr + 4 * i) * 257 + tc + 64 * j] = acc[i][j] + bb;
    }
    __syncthreads();

    // ---- phase 3: per-type heads; select type per variant
    const float ml = *max_logit;
    for (int t = 0; t < 3; t++) {
        if (tid < 32) logits_s[tid] = 0.f;
        #pragma unroll
        for (int i = 0; i < 8; i++)
            #pragma unroll
            for (int j = 0; j < 4; j++) acc[i][j] = 0.f;

        for (int kb = 0; kb < 4; kb++) {
            for (int idx = tid; idx < 64 * H; idx += 256)
                ws[idx] = outW1[t * H * H + kb * 64 * H + idx];
            __syncthreads();
            for (int k = 0; k < 64; k++) {
                float a[8], b[4];
                #pragma unroll
                for (int i = 0; i < 8; i++) a[i] = z1s[(tr + 4 * i) * 257 + kb * 64 + k];
                #pragma unroll
                for (int j = 0; j < 4; j++) b[j] = ws[k * H + tc + 64 * j];
                #pragma unroll
                for (int i = 0; i < 8; i++)
                    #pragma unroll
                    for (int j = 0; j < 4; j++) acc[i][j] = fmaf(a[i], b[j], acc[i][j]);
            }
            __syncthreads();
        }

        // o = lrelu(acc + b1t); partial dot with W2t column
        float partial[8];
        #pragma unroll
        for (int i = 0; i < 8; i++) partial[i] = 0.f;
        #pragma unroll
        for (int j = 0; j < 4; j++) {
            const int c = tc + 64 * j;
            const float bb = outb1[t * H + c];
            const float w2 = outW2[t * H + c];
            #pragma unroll
            for (int i = 0; i < 8; i++)
                partial[i] += lrelu(acc[i][j] + bb) * w2;
        }
        #pragma unroll
        for (int i = 0; i < 8; i++) {
            float p = partial[i];
            #pragma unroll
            for (int off = 16; off; off >>= 1)
                p += __shfl_xor_sync(0xffffffffu, p, off);
            if ((tid & 31) == 0) atomicAdd(&logits_s[tr + 4 * i], p);
        }
        __syncthreads();
        if (tid < 32) {
            const int v = v0 + tid;
            if (vtypes[v] == t) {
                float l = logits_s[tid] + outb2[t];
                const int ci = min(g_alt_cnt[v], MAX_ALT);
                l *= conf[ci];
                out[v] = ml * tanhf(l / ml);
            }
        }
        __syncthreads();
    }
}

// ---------------- launch ----------------
extern "C" void kernel_launch(void* const* d_in, const int* in_sizes, int n_in,
                              void* d_out, int out_size)
{
    const float* reads  = (const float*)d_in[0];
    const float* info   = (const float*)d_in[1];
    const int*   refseg = (const int*)  d_in[2];
    const int*   altseg = (const int*)  d_in[3];
    const int*   vtypes = (const int*)  d_in[4];
    const float* phiW0  = (const float*)d_in[5];
    const float* phib0  = (const float*)d_in[6];
    const float* phiW1  = (const float*)d_in[7];
    const float* phib1  = (const float*)d_in[8];
    const float* omW0   = (const float*)d_in[9];
    const float* omb0   = (const float*)d_in[10];
    const float* rhoW0  = (const float*)d_in[11];
    const float* rhob0  = (const float*)d_in[12];
    const float* rhoW1  = (const float*)d_in[13];
    const float* rhob1  = (const float*)d_in[14];
    const float* outW1  = (const float*)d_in[15];
    const float* outb1  = (const float*)d_in[16];
    const float* outW2  = (const float*)d_in[17];
    const float* outb2  = (const float*)d_in[18];
    const float* conf   = (const float*)d_in[19];
    const float* maxl   = (const float*)d_in[20];
    float* out = (float*)d_out;

    cudaFuncSetAttribute(phi_kernel,  cudaFuncAttributeMaxDynamicSharedMemorySize, PHI_SMEM_BYTES);
    cudaFuncSetAttribute(head_kernel, cudaFuncAttributeMaxDynamicSharedMemorySize, HEAD_SMEM_BYTES);

    zero_kernel<<<(V * H + 255) / 256, 256>>>();
    phi_kernel<<<(NREF + NALT) / TILE_R, 512, PHI_SMEM_BYTES>>>(
        reads, refseg, altseg, phiW0, phib0, phiW1, phib1);
    build_X_kernel<<<V / 8, 256>>>(info, omW0, omb0);
    head_kernel<<<V / 32, 256, HEAD_SMEM_BYTES>>>(
        vtypes, rhoW0, rhob0, rhoW1, rhob1,
        outW1, outb1, outW2, outb2, conf, maxl, out);
}

// round 3
// speedup vs baseline: 1.7742x; 1.7742x over previous
#include <cuda_runtime.h>
#include <cuda_bf16.h>
#include <math.h>
#include <stdint.h>

#define V     8192
#define NREF  262144
#define NALT  131072
#define FREAD 11
#define FINFO 9
#define H     256
#define MAX_ALT 10

#define TILE_R 128

// ---------------- scratch ----------------
__device__ float g_ref_sums[V * H];
__device__ float g_alt_sums[V * H];
__device__ int   g_ref_cnt[V];
__device__ int   g_alt_cnt[V];
__device__ float g_X[V * 3 * H];
// W1 bf16 hi/lo in mma-fragment-linear order: [kt(16)][nt(32)][lane(32)][reg(2)] uint32
__device__ __align__(16) uint32_t g_W1hf[16 * 32 * 32 * 2];
__device__ __align__(16) uint32_t g_W1lf[16 * 32 * 32 * 2];

// ---------------- helpers ----------------
__device__ __forceinline__ float lrelu(float x) { return x > 0.f ? x : 0.01f * x; }
__device__ __forceinline__ float sigmoidf_(float x) { return 1.f / (1.f + __expf(-x)); }

__device__ __forceinline__ uint32_t pack_bf16x2(__nv_bfloat16 lo16, __nv_bfloat16 hi16) {
    return ((uint32_t)__bfloat16_as_ushort(hi16) << 16) | (uint32_t)__bfloat16_as_ushort(lo16);
}

__device__ __forceinline__ void mma16816(float* c, const uint32_t* a, uint32_t b0, uint32_t b1) {
    asm volatile(
        "mma.sync.aligned.m16n8k16.row.col.f32.bf16.bf16.f32 "
        "{%0,%1,%2,%3}, {%4,%5,%6,%7}, {%8,%9}, {%0,%1,%2,%3};"
        : "+f"(c[0]), "+f"(c[1]), "+f"(c[2]), "+f"(c[3])
        : "r"(a[0]), "r"(a[1]), "r"(a[2]), "r"(a[3]), "r"(b0), "r"(b1));
}

__device__ __forceinline__ void ldmatrix4(uint32_t* r, uint32_t addr) {
    asm volatile("ldmatrix.sync.aligned.m8n8.x4.shared.b16 {%0,%1,%2,%3}, [%4];"
                 : "=r"(r[0]), "=r"(r[1]), "=r"(r[2]), "=r"(r[3]) : "r"(addr));
}

// ---------------- kernel 0: zero accumulators ----------------
__global__ void zero_kernel() {
    int idx = blockIdx.x * blockDim.x + threadIdx.x;
    if (idx < V * H) { g_ref_sums[idx] = 0.f; g_alt_sums[idx] = 0.f; }
    if (idx < V)     { g_ref_cnt[idx] = 0;    g_alt_cnt[idx] = 0; }
}

// ---------------- kernel 0b: W1 -> bf16 hi/lo mma fragments ----------------
// idx = kt*1024 + nt*32 + lane ; per thread 2 regs (k-halves)
__global__ void convW1_kernel(const float* __restrict__ W1) {
    const int idx = blockIdx.x * blockDim.x + threadIdx.x;   // 0..16383
    const int lane = idx & 31;
    const int nt   = (idx >> 5) & 31;
    const int kt   = idx >> 10;
    const int n = nt * 8 + (lane >> 2);
    const int kbase = kt * 16 + (lane & 3) * 2;
    #pragma unroll
    for (int r = 0; r < 2; r++) {
        const int k = kbase + 8 * r;
        const float w0 = W1[k * 256 + n];
        const float w1 = W1[(k + 1) * 256 + n];
        __nv_bfloat16 h0 = __float2bfloat16(w0), h1 = __float2bfloat16(w1);
        __nv_bfloat16 l0 = __float2bfloat16(w0 - __bfloat162float(h0));
        __nv_bfloat16 l1 = __float2bfloat16(w1 - __bfloat162float(h1));
        g_W1hf[idx * 2 + r] = pack_bf16x2(h0, h1);
        g_W1lf[idx * 2 + r] = pack_bf16x2(l0, l1);
    }
}

// ---------------- kernel 1: fused phi MLP (mma.sync bf16 split) + segment reduce ----------------
// smem: hsH[128][264 bf16] | hsL[...] | xsT[11][128] f32 | segs[128]
// ys[128][257] f32 reuses hsH/hsL region after the MMA phase.
#define HPITCH_B 528                      // 264 bf16 = 528 bytes (33 x 16B, conflict-free ldmatrix)
#define SM_HSH   0
#define SM_HSL   (128 * HPITCH_B)         // 67584
#define SM_XST   (2 * 128 * HPITCH_B)     // 135168
#define SM_SEGS  (SM_XST + 11 * 128 * 4)  // 140800
#define PHI_SMEM_TOTAL (SM_SEGS + 512)    // 141312
#define YPITCH 257

__global__ __launch_bounds__(512, 1) void phi_mma_kernel(
    const float* __restrict__ reads,
    const int* __restrict__ ref_seg, const int* __restrict__ alt_seg,
    const float* __restrict__ W0, const float* __restrict__ b0,
    const float* __restrict__ b1)
{
    extern __shared__ char sm[];
    const uint32_t smb = (uint32_t)__cvta_generic_to_shared(sm);
    float* xsT  = (float*)(sm + SM_XST);
    int*   segs = (int*)(sm + SM_SEGS);
    float* ys   = (float*)sm;

    const int tid = threadIdx.x;
    const long base = (long)blockIdx.x * TILE_R;
    const bool is_alt = (base >= NREF);
    const int* seg_src = is_alt ? (alt_seg + (base - NREF)) : (ref_seg + base);

    // load reads transposed + segment ids
    for (int idx = tid; idx < TILE_R * FREAD; idx += 512) {
        int r = idx / FREAD, c = idx % FREAD;
        xsT[c * 128 + r] = reads[(base + r) * FREAD + c];
    }
    if (tid < TILE_R) segs[tid] = seg_src[tid];
    __syncthreads();

    // ---- stage 1: h = lrelu(x @ W0 + b0) -> bf16 hi/lo in smem
    {
        const int j = tid & 255;
        const int rbase = (tid >> 8) * 64;
        float w[FREAD];
        #pragma unroll
        for (int k = 0; k < FREAD; k++) w[k] = W0[k * H + j];
        const float bb = b0[j];
        for (int r = rbase; r < rbase + 64; r += 4) {
            float a0 = bb, a1 = bb, a2 = bb, a3 = bb;
            #pragma unroll
            for (int k = 0; k < FREAD; k++) {
                const float4 a = *(const float4*)&xsT[k * 128 + r];
                a0 = fmaf(a.x, w[k], a0); a1 = fmaf(a.y, w[k], a1);
                a2 = fmaf(a.z, w[k], a2); a3 = fmaf(a.w, w[k], a3);
            }
            float hv[4] = {lrelu(a0), lrelu(a1), lrelu(a2), lrelu(a3)};
            #pragma unroll
            for (int q = 0; q < 4; q++) {
                __nv_bfloat16 hi = __float2bfloat16(hv[q]);
                __nv_bfloat16 lo = __float2bfloat16(hv[q] - __bfloat162float(hi));
                const int off = (r + q) * HPITCH_B + j * 2;
                *(__nv_bfloat16*)(sm + SM_HSH + off) = hi;
                *(__nv_bfloat16*)(sm + SM_HSL + off) = lo;
            }
        }
    }
    __syncthreads();

    // ---- stage 2: D = h @ W1 via mma.sync, 3-term bf16 split
    const int wid = tid >> 5, lane = tid & 31;
    const int wr = wid >> 2, wc = wid & 3;          // 4x4 warp grid
    const int rowbase = wr * 32;

    float acc[2][8][4];
    #pragma unroll
    for (int mt = 0; mt < 2; mt++)
        #pragma unroll
        for (int j = 0; j < 8; j++)
            #pragma unroll
            for (int q = 0; q < 4; q++) acc[mt][j][q] = 0.f;

    for (int kt = 0; kt < 16; kt++) {
        uint32_t ah[2][4], al[2][4];
        #pragma unroll
        for (int mt = 0; mt < 2; mt++) {
            const uint32_t addr = smb + SM_HSH
                + (uint32_t)(rowbase + mt * 16 + (lane & 15)) * HPITCH_B
                + ((uint32_t)(lane >> 4)) * 16 + (uint32_t)kt * 32;
            ldmatrix4(ah[mt], addr);
            ldmatrix4(al[mt], addr + (SM_HSL - SM_HSH));
        }
        const uint2* bh = (const uint2*)g_W1hf + ((kt * 32 + wc * 8) * 32 + lane);
        const uint2* bl = (const uint2*)g_W1lf + ((kt * 32 + wc * 8) * 32 + lane);
        #pragma unroll
        for (int j = 0; j < 8; j++) {
            const uint2 Bh = __ldg(bh + j * 32);
            const uint2 Bl = __ldg(bl + j * 32);
            #pragma unroll
            for (int mt = 0; mt < 2; mt++) {
                mma16816(acc[mt][j], ah[mt], Bh.x, Bh.y);
                mma16816(acc[mt][j], ah[mt], Bl.x, Bl.y);
                mma16816(acc[mt][j], al[mt], Bh.x, Bh.y);
            }
        }
    }
    __syncthreads();   // all ldmatrix reads done before ys overwrites hs

    // ---- epilogue: bias + sigmoid -> ys[128][257]
    {
        const int colb = wc * 64 + 2 * (lane & 3);
        float bias0[8], bias1[8];
        #pragma unroll
        for (int j = 0; j < 8; j++) {
            bias0[j] = __ldg(&b1[colb + j * 8]);
            bias1[j] = __ldg(&b1[colb + j * 8 + 1]);
        }
        #pragma unroll
        for (int mt = 0; mt < 2; mt++) {
            const int row = rowbase + mt * 16 + (lane >> 2);
            #pragma unroll
            for (int j = 0; j < 8; j++) {
                const int col = colb + j * 8;
                ys[row * YPITCH + col]           = sigmoidf_(acc[mt][j][0] + bias0[j]);
                ys[row * YPITCH + col + 1]       = sigmoidf_(acc[mt][j][1] + bias1[j]);
                ys[(row + 8) * YPITCH + col]     = sigmoidf_(acc[mt][j][2] + bias0[j]);
                ys[(row + 8) * YPITCH + col + 1] = sigmoidf_(acc[mt][j][3] + bias1[j]);
            }
        }
    }
    __syncthreads();

    // ---- sorted-run segment reduction
    float* sums = is_alt ? g_alt_sums : g_ref_sums;
    if (tid < H) {
        const int c = tid;
        int cur = segs[0];
        float a = 0.f;
        for (int r = 0; r < TILE_R; r++) {
            int s = segs[r];
            if (s != cur) { atomicAdd(&sums[cur * H + c], a); a = 0.f; cur = s; }
            a += ys[r * YPITCH + c];
        }
        atomicAdd(&sums[cur * H + c], a);
    } else if (tid == H) {
        int* cnt = is_alt ? g_alt_cnt : g_ref_cnt;
        int cur = segs[0], n = 0;
        for (int r = 0; r < TILE_R; r++) {
            int s = segs[r];
            if (s != cur) { atomicAdd(&cnt[cur], n); n = 0; cur = s; }
            n++;
        }
        atomicAdd(&cnt[cur], n);
    }
}

// ---------------- kernel 2: build X ----------------
__global__ __launch_bounds__(256) void build_X_kernel(
    const float* __restrict__ info,
    const float* __restrict__ omW0, const float* __restrict__ omb0)
{
    const int c = threadIdx.x;
    const int v0 = blockIdx.x * 8;
    float w[FINFO];
    #pragma unroll
    for (int k = 0; k < FINFO; k++) w[k] = omW0[k * H + c];
    const float bb = omb0[c];
    for (int vl = 0; vl < 8; vl++) {
        const int v = v0 + vl;
        const float rc = (float)max(g_ref_cnt[v], 1);
        const float ac = (float)max(g_alt_cnt[v], 1);
        g_X[v * 768 + c]       = g_ref_sums[v * H + c] / rc;
        g_X[v * 768 + 256 + c] = g_alt_sums[v * H + c] / ac;
        float z = bb;
        #pragma unroll
        for (int k = 0; k < FINFO; k++) z = fmaf(__ldg(&info[v * FINFO + k]), w[k], z);
        g_X[v * 768 + 512 + c] = sigmoidf_(z);
    }
}

// ---------------- kernel 3: rho MLP + per-type heads ----------------
#define HEAD_SMEM_FLOATS (64 * H + 32 * 257 + 32 * 65 + 32)
#define HEAD_SMEM_BYTES  (HEAD_SMEM_FLOATS * 4)

__global__ __launch_bounds__(256, 2) void head_kernel(
    const int* __restrict__ vtypes,
    const float* __restrict__ rhoW0, const float* __restrict__ rhob0,
    const float* __restrict__ rhoW1, const float* __restrict__ rhob1,
    const float* __restrict__ outW1, const float* __restrict__ outb1,
    const float* __restrict__ outW2, const float* __restrict__ outb2,
    const float* __restrict__ conf,  const float* __restrict__ max_logit,
    float* __restrict__ out)
{
    extern __shared__ float smem[];
    float* ws       = smem;
    float* z1s      = ws + 64 * H;
    float* xs       = z1s + 32 * 257;
    float* logits_s = xs + 32 * 65;

    const int tid = threadIdx.x;
    const int tr = tid >> 6;
    const int tc = tid & 63;
    const int v0 = blockIdx.x * 32;

    float acc[8][4];

    // phase 1: z1 = lrelu(X @ rhoW0 + rhob0)
    #pragma unroll
    for (int i = 0; i < 8; i++)
        #pragma unroll
        for (int j = 0; j < 4; j++) acc[i][j] = 0.f;

    for (int kb = 0; kb < 12; kb++) {
        for (int idx = tid; idx < 32 * 64; idx += 256) {
            int r = idx >> 6, k = idx & 63;
            xs[r * 65 + k] = g_X[(v0 + r) * 768 + kb * 64 + k];
        }
        for (int idx = tid; idx < 64 * H; idx += 256)
            ws[idx] = rhoW0[kb * 64 * H + idx];
        __syncthreads();
        for (int k = 0; k < 64; k++) {
            float a[8], b[4];
            #pragma unroll
            for (int i = 0; i < 8; i++) a[i] = xs[(tr + 4 * i) * 65 + k];
            #pragma unroll
            for (int j = 0; j < 4; j++) b[j] = ws[k * H + tc + 64 * j];
            #pragma unroll
            for (int i = 0; i < 8; i++)
                #pragma unroll
                for (int j = 0; j < 4; j++) acc[i][j] = fmaf(a[i], b[j], acc[i][j]);
        }
        __syncthreads();
    }
    #pragma unroll
    for (int j = 0; j < 4; j++) {
        const float bb = rhob0[tc + 64 * j];
        #pragma unroll
        for (int i = 0; i < 8; i++)
            z1s[(tr + 4 * i) * 257 + tc + 64 * j] = lrelu(acc[i][j] + bb);
    }
    __syncthreads();

    // phase 2: agg = z1 @ rhoW1 + rhob1
    #pragma unroll
    for (int i = 0; i < 8; i++)
        #pragma unroll
        for (int j = 0; j < 4; j++) acc[i][j] = 0.f;

    for (int kb = 0; kb < 4; kb++) {
        for (int idx = tid; idx < 64 * H; idx += 256)
            ws[idx] = rhoW1[kb * 64 * H + idx];
        __syncthreads();
        for (int k = 0; k < 64; k++) {
            float a[8], b[4];
            #pragma unroll
            for (int i = 0; i < 8; i++) a[i] = z1s[(tr + 4 * i) * 257 + kb * 64 + k];
            #pragma unroll
            for (int j = 0; j < 4; j++) b[j] = ws[k * H + tc + 64 * j];
            #pragma unroll
            for (int i = 0; i < 8; i++)
                #pragma unroll
                for (int j = 0; j < 4; j++) acc[i][j] = fmaf(a[i], b[j], acc[i][j]);
        }
        __syncthreads();
    }
    #pragma unroll
    for (int j = 0; j < 4; j++) {
        const float bb = rhob1[tc + 64 * j];
        #pragma unroll
        for (int i = 0; i < 8; i++)
            z1s[(tr + 4 * i) * 257 + tc + 64 * j] = acc[i][j] + bb;
    }
    __syncthreads();

    // phase 3: per-type heads
    const float ml = *max_logit;
    for (int t = 0; t < 3; t++) {
        if (tid < 32) logits_s[tid] = 0.f;
        #pragma unroll
        for (int i = 0; i < 8; i++)
            #pragma unroll
            for (int j = 0; j < 4; j++) acc[i][j] = 0.f;

        for (int kb = 0; kb < 4; kb++) {
            for (int idx = tid; idx < 64 * H; idx += 256)
                ws[idx] = outW1[t * H * H + kb * 64 * H + idx];
            __syncthreads();
            for (int k = 0; k < 64; k++) {
                float a[8], b[4];
                #pragma unroll
                for (int i = 0; i < 8; i++) a[i] = z1s[(tr + 4 * i) * 257 + kb * 64 + k];
                #pragma unroll
                for (int j = 0; j < 4; j++) b[j] = ws[k * H + tc + 64 * j];
                #pragma unroll
                for (int i = 0; i < 8; i++)
                    #pragma unroll
                    for (int j = 0; j < 4; j++) acc[i][j] = fmaf(a[i], b[j], acc[i][j]);
            }
            __syncthreads();
        }

        float partial[8];
        #pragma unroll
        for (int i = 0; i < 8; i++) partial[i] = 0.f;
        #pragma unroll
        for (int j = 0; j < 4; j++) {
            const int c = tc + 64 * j;
            const float bb = outb1[t * H + c];
            const float w2 = outW2[t * H + c];
            #pragma unroll
            for (int i = 0; i < 8; i++)
                partial[i] += lrelu(acc[i][j] + bb) * w2;
        }
        #pragma unroll
        for (int i = 0; i < 8; i++) {
            float p = partial[i];
            #pragma unroll
            for (int off = 16; off; off >>= 1)
                p += __shfl_xor_sync(0xffffffffu, p, off);
            if ((tid & 31) == 0) atomicAdd(&logits_s[tr + 4 * i], p);
        }
        __syncthreads();
        if (tid < 32) {
            const int v = v0 + tid;
            if (vtypes[v] == t) {
                float l = logits_s[tid] + outb2[t];
                const int ci = min(g_alt_cnt[v], MAX_ALT);
                l *= conf[ci];
                out[v] = ml * tanhf(l / ml);
            }
        }
        __syncthreads();
    }
}

// ---------------- launch ----------------
extern "C" void kernel_launch(void* const* d_in, const int* in_sizes, int n_in,
                              void* d_out, int out_size)
{
    const float* reads  = (const float*)d_in[0];
    const float* info   = (const float*)d_in[1];
    const int*   refseg = (const int*)  d_in[2];
    const int*   altseg = (const int*)  d_in[3];
    const int*   vtypes = (const int*)  d_in[4];
    const float* phiW0  = (const float*)d_in[5];
    const float* phib0  = (const float*)d_in[6];
    const float* phiW1  = (const float*)d_in[7];
    const float* phib1  = (const float*)d_in[8];
    const float* omW0   = (const float*)d_in[9];
    const float* omb0   = (const float*)d_in[10];
    const float* rhoW0  = (const float*)d_in[11];
    const float* rhob0  = (const float*)d_in[12];
    const float* rhoW1  = (const float*)d_in[13];
    const float* rhob1  = (const float*)d_in[14];
    const float* outW1  = (const float*)d_in[15];
    const float* outb1  = (const float*)d_in[16];
    const float* outW2  = (const float*)d_in[17];
    const float* outb2  = (const float*)d_in[18];
    const float* conf   = (const float*)d_in[19];
    const float* maxl   = (const float*)d_in[20];
    float* out = (float*)d_out;

    cudaFuncSetAttribute(phi_mma_kernel, cudaFuncAttributeMaxDynamicSharedMemorySize, PHI_SMEM_TOTAL);
    cudaFuncSetAttribute(head_kernel,    cudaFuncAttributeMaxDynamicSharedMemorySize, HEAD_SMEM_BYTES);

    zero_kernel<<<(V * H + 255) / 256, 256>>>();
    convW1_kernel<<<64, 256>>>(phiW1);
    phi_mma_kernel<<<(NREF + NALT) / TILE_R, 512, PHI_SMEM_TOTAL>>>(
        reads, refseg, altseg, phiW0, phib0, phib1);
    build_X_kernel<<<V / 8, 256>>>(info, omW0, omb0);
    head_kernel<<<V / 32, 256, HEAD_SMEM_BYTES>>>(
        vtypes, rhoW0, rhob0, rhoW1, rhob1,
        outW1, outb1, outW2, outb2, conf, maxl, out);
}

// round 4
// speedup vs baseline: 2.3314x; 1.3141x over previous
#include <cuda_runtime.h>
#include <cuda_bf16.h>
#include <math.h>
#include <stdint.h>

#define V     8192
#define NREF  262144
#define NALT  131072
#define FREAD 11
#define FINFO 9
#define H     256
#define MAX_ALT 10

#define TILE_R 128

// ---------------- scratch ----------------
__device__ float g_ref_sums[V * H];
__device__ float g_alt_sums[V * H];
__device__ int   g_ref_cnt[V];
__device__ int   g_alt_cnt[V];
// X split into bf16 hi/lo, row-major [V][768]
__device__ __align__(16) __nv_bfloat16 g_Xh[V * 768];
__device__ __align__(16) __nv_bfloat16 g_Xl[V * 768];
// weights in mma-fragment-linear order: [kt][nt(32)][lane(32)][reg(2)] uint32
__device__ __align__(16) uint32_t g_W1hf[16 * 2048];   // phi W1 (K=256)
__device__ __align__(16) uint32_t g_W1lf[16 * 2048];
__device__ __align__(16) uint32_t g_r0h[48 * 2048];    // rho W0 (K=768)
__device__ __align__(16) uint32_t g_r0l[48 * 2048];
__device__ __align__(16) uint32_t g_r1h[16 * 2048];    // rho W1 (K=256)
__device__ __align__(16) uint32_t g_r1l[16 * 2048];
__device__ __align__(16) uint32_t g_oWh[48 * 2048];    // out W1 [3](K=256)
__device__ __align__(16) uint32_t g_oWl[48 * 2048];

// ---------------- helpers ----------------
__device__ __forceinline__ float lrelu(float x) { return x > 0.f ? x : 0.01f * x; }
__device__ __forceinline__ float sigmoidf_(float x) { return 1.f / (1.f + __expf(-x)); }

__device__ __forceinline__ uint32_t pack_bf16x2(__nv_bfloat16 lo16, __nv_bfloat16 hi16) {
    return ((uint32_t)__bfloat16_as_ushort(hi16) << 16) | (uint32_t)__bfloat16_as_ushort(lo16);
}

__device__ __forceinline__ void mma16816(float* c, const uint32_t* a, uint32_t b0, uint32_t b1) {
    asm volatile(
        "mma.sync.aligned.m16n8k16.row.col.f32.bf16.bf16.f32 "
        "{%0,%1,%2,%3}, {%4,%5,%6,%7}, {%8,%9}, {%0,%1,%2,%3};"
        : "+f"(c[0]), "+f"(c[1]), "+f"(c[2]), "+f"(c[3])
        : "r"(a[0]), "r"(a[1]), "r"(a[2]), "r"(a[3]), "r"(b0), "r"(b1));
}

__device__ __forceinline__ void ldmatrix4(uint32_t* r, uint32_t addr) {
    asm volatile("ldmatrix.sync.aligned.m8n8.x4.shared.b16 {%0,%1,%2,%3}, [%4];"
                 : "=r"(r[0]), "=r"(r[1]), "=r"(r[2]), "=r"(r[3]) : "r"(addr));
}

// ---------------- kernel 0: zero accumulators ----------------
__global__ void zero_kernel() {
    int idx = blockIdx.x * blockDim.x + threadIdx.x;
    if (idx < V * H) { g_ref_sums[idx] = 0.f; g_alt_sums[idx] = 0.f; }
    if (idx < V)     { g_ref_cnt[idx] = 0;    g_alt_cnt[idx] = 0; }
}

// ---------------- kernel 0b: generic W[K][256] -> bf16 hi/lo mma fragments ----------------
__global__ void convW_frag(const float* __restrict__ W, int ktot,
                           uint32_t* __restrict__ dh, uint32_t* __restrict__ dl) {
    const int idx = blockIdx.x * blockDim.x + threadIdx.x;
    if (idx >= ktot * 1024) return;
    const int lane = idx & 31;
    const int nt   = (idx >> 5) & 31;
    const int kt   = idx >> 10;
    const int n = nt * 8 + (lane >> 2);
    const int kbase = kt * 16 + (lane & 3) * 2;
    #pragma unroll
    for (int r = 0; r < 2; r++) {
        const int k = kbase + 8 * r;
        const float w0 = W[k * 256 + n];
        const float w1 = W[(k + 1) * 256 + n];
        __nv_bfloat16 h0 = __float2bfloat16(w0), h1 = __float2bfloat16(w1);
        __nv_bfloat16 l0 = __float2bfloat16(w0 - __bfloat162float(h0));
        __nv_bfloat16 l1 = __float2bfloat16(w1 - __bfloat162float(h1));
        dh[idx * 2 + r] = pack_bf16x2(h0, h1);
        dl[idx * 2 + r] = pack_bf16x2(l0, l1);
    }
}

// ---------------- kernel 1: fused phi MLP (mma.sync bf16 split) + segment reduce ----------------
#define HPITCH_B 528
#define SM_HSH   0
#define SM_HSL   (128 * HPITCH_B)
#define SM_XST   (2 * 128 * HPITCH_B)
#define SM_SEGS  (SM_XST + 11 * 128 * 4)
#define PHI_SMEM_TOTAL (SM_SEGS + 512)
#define YPITCH 257

__global__ __launch_bounds__(512, 1) void phi_mma_kernel(
    const float* __restrict__ reads,
    const int* __restrict__ ref_seg, const int* __restrict__ alt_seg,
    const float* __restrict__ W0, const float* __restrict__ b0,
    const float* __restrict__ b1)
{
    extern __shared__ char sm[];
    const uint32_t smb = (uint32_t)__cvta_generic_to_shared(sm);
    float* xsT  = (float*)(sm + SM_XST);
    int*   segs = (int*)(sm + SM_SEGS);
    float* ys   = (float*)sm;

    const int tid = threadIdx.x;
    const long base = (long)blockIdx.x * TILE_R;
    const bool is_alt = (base >= NREF);
    const int* seg_src = is_alt ? (alt_seg + (base - NREF)) : (ref_seg + base);

    for (int idx = tid; idx < TILE_R * FREAD; idx += 512) {
        int r = idx / FREAD, c = idx % FREAD;
        xsT[c * 128 + r] = reads[(base + r) * FREAD + c];
    }
    if (tid < TILE_R) segs[tid] = seg_src[tid];
    __syncthreads();

    // stage 1: h = lrelu(x @ W0 + b0) -> bf16 hi/lo in smem
    {
        const int j = tid & 255;
        const int rbase = (tid >> 8) * 64;
        float w[FREAD];
        #pragma unroll
        for (int k = 0; k < FREAD; k++) w[k] = W0[k * H + j];
        const float bb = b0[j];
        for (int r = rbase; r < rbase + 64; r += 4) {
            float a0 = bb, a1 = bb, a2 = bb, a3 = bb;
            #pragma unroll
            for (int k = 0; k < FREAD; k++) {
                const float4 a = *(const float4*)&xsT[k * 128 + r];
                a0 = fmaf(a.x, w[k], a0); a1 = fmaf(a.y, w[k], a1);
                a2 = fmaf(a.z, w[k], a2); a3 = fmaf(a.w, w[k], a3);
            }
            float hv[4] = {lrelu(a0), lrelu(a1), lrelu(a2), lrelu(a3)};
            #pragma unroll
            for (int q = 0; q < 4; q++) {
                __nv_bfloat16 hi = __float2bfloat16(hv[q]);
                __nv_bfloat16 lo = __float2bfloat16(hv[q] - __bfloat162float(hi));
                const int off = (r + q) * HPITCH_B + j * 2;
                *(__nv_bfloat16*)(sm + SM_HSH + off) = hi;
                *(__nv_bfloat16*)(sm + SM_HSL + off) = lo;
            }
        }
    }
    __syncthreads();

    // stage 2: D = h @ W1 via mma.sync, 3-term bf16 split
    const int wid = tid >> 5, lane = tid & 31;
    const int wr = wid >> 2, wc = wid & 3;
    const int rowbase = wr * 32;

    float acc[2][8][4];
    #pragma unroll
    for (int mt = 0; mt < 2; mt++)
        #pragma unroll
        for (int j = 0; j < 8; j++)
            #pragma unroll
            for (int q = 0; q < 4; q++) acc[mt][j][q] = 0.f;

    for (int kt = 0; kt < 16; kt++) {
        uint32_t ah[2][4], al[2][4];
        #pragma unroll
        for (int mt = 0; mt < 2; mt++) {
            const uint32_t addr = smb + SM_HSH
                + (uint32_t)(rowbase + mt * 16 + (lane & 15)) * HPITCH_B
                + ((uint32_t)(lane >> 4)) * 16 + (uint32_t)kt * 32;
            ldmatrix4(ah[mt], addr);
            ldmatrix4(al[mt], addr + (SM_HSL - SM_HSH));
        }
        const uint2* bh = (const uint2*)g_W1hf + ((kt * 32 + wc * 8) * 32 + lane);
        const uint2* bl = (const uint2*)g_W1lf + ((kt * 32 + wc * 8) * 32 + lane);
        #pragma unroll
        for (int j = 0; j < 8; j++) {
            const uint2 Bh = __ldg(bh + j * 32);
            const uint2 Bl = __ldg(bl + j * 32);
            #pragma unroll
            for (int mt = 0; mt < 2; mt++) {
                mma16816(acc[mt][j], ah[mt], Bh.x, Bh.y);
                mma16816(acc[mt][j], ah[mt], Bl.x, Bl.y);
                mma16816(acc[mt][j], al[mt], Bh.x, Bh.y);
            }
        }
    }
    __syncthreads();

    // epilogue: bias + sigmoid -> ys[128][257]
    {
        const int colb = wc * 64 + 2 * (lane & 3);
        float bias0[8], bias1[8];
        #pragma unroll
        for (int j = 0; j < 8; j++) {
            bias0[j] = __ldg(&b1[colb + j * 8]);
            bias1[j] = __ldg(&b1[colb + j * 8 + 1]);
        }
        #pragma unroll
        for (int mt = 0; mt < 2; mt++) {
            const int row = rowbase + mt * 16 + (lane >> 2);
            #pragma unroll
            for (int j = 0; j < 8; j++) {
                const int col = colb + j * 8;
                ys[row * YPITCH + col]           = sigmoidf_(acc[mt][j][0] + bias0[j]);
                ys[row * YPITCH + col + 1]       = sigmoidf_(acc[mt][j][1] + bias1[j]);
                ys[(row + 8) * YPITCH + col]     = sigmoidf_(acc[mt][j][2] + bias0[j]);
                ys[(row + 8) * YPITCH + col + 1] = sigmoidf_(acc[mt][j][3] + bias1[j]);
            }
        }
    }
    __syncthreads();

    // sorted-run segment reduction
    float* sums = is_alt ? g_alt_sums : g_ref_sums;
    if (tid < H) {
        const int c = tid;
        int cur = segs[0];
        float a = 0.f;
        for (int r = 0; r < TILE_R; r++) {
            int s = segs[r];
            if (s != cur) { atomicAdd(&sums[cur * H + c], a); a = 0.f; cur = s; }
            a += ys[r * YPITCH + c];
        }
        atomicAdd(&sums[cur * H + c], a);
    } else if (tid == H) {
        int* cnt = is_alt ? g_alt_cnt : g_ref_cnt;
        int cur = segs[0], n = 0;
        for (int r = 0; r < TILE_R; r++) {
            int s = segs[r];
            if (s != cur) { atomicAdd(&cnt[cur], n); n = 0; cur = s; }
            n++;
        }
        atomicAdd(&cnt[cur], n);
    }
}

// ---------------- kernel 2: build split X = [ref_mean | alt_mean | omega] (bf16 hi/lo) ----------------
__global__ __launch_bounds__(256) void build_X_kernel(
    const float* __restrict__ info,
    const float* __restrict__ omW0, const float* __restrict__ omb0)
{
    const int c = threadIdx.x;
    const int v0 = blockIdx.x * 8;
    float w[FINFO];
    #pragma unroll
    for (int k = 0; k < FINFO; k++) w[k] = omW0[k * H + c];
    const float bb = omb0[c];
    for (int vl = 0; vl < 8; vl++) {
        const int v = v0 + vl;
        const float rc = (float)max(g_ref_cnt[v], 1);
        const float ac = (float)max(g_alt_cnt[v], 1);
        float vals[3];
        vals[0] = g_ref_sums[v * H + c] / rc;
        vals[1] = g_alt_sums[v * H + c] / ac;
        float z = bb;
        #pragma unroll
        for (int k = 0; k < FINFO; k++) z = fmaf(__ldg(&info[v * FINFO + k]), w[k], z);
        vals[2] = sigmoidf_(z);
        #pragma unroll
        for (int p = 0; p < 3; p++) {
            const int idx = v * 768 + p * 256 + c;
            __nv_bfloat16 hi = __float2bfloat16(vals[p]);
            g_Xh[idx] = hi;
            g_Xl[idx] = __float2bfloat16(vals[p] - __bfloat162float(hi));
        }
    }
}

// ---------------- kernel 3: rho MLP + per-type heads (mma.sync bf16 split) ----------------
// Block = 32 variants, 256 threads = 8 warps (wr 0..1 rows 16, wc 0..3 cols 64)
// smem: xa hi/lo (X chunk / later agg) | z1 hi/lo | logits
#define SM_XH   0
#define SM_XL   16896
#define SM_Z1H  33792
#define SM_Z1L  50688
#define SM_LOG  67584
#define HEAD_SMEM_TOTAL 67840

__global__ __launch_bounds__(256, 2) void head_mma_kernel(
    const int* __restrict__ vtypes,
    const float* __restrict__ rhob0, const float* __restrict__ rhob1,
    const float* __restrict__ outb1, const float* __restrict__ outb2,
    const float* __restrict__ outW2,
    const float* __restrict__ conf,  const float* __restrict__ max_logit,
    float* __restrict__ out)
{
    extern __shared__ char sm[];
    const uint32_t smb = (uint32_t)__cvta_generic_to_shared(sm);
    float* logits_s = (float*)(sm + SM_LOG);

    const int tid = threadIdx.x;
    const int wid = tid >> 5, lane = tid & 31;
    const int wr = wid >> 2, wc = wid & 3;
    const int v0 = blockIdx.x * 32;

    float acc[8][4];

    // ---- phase 1: z1 = lrelu(X @ rhoW0 + rhob0), K = 768 in 3 chunks of 256
    #pragma unroll
    for (int j = 0; j < 8; j++)
        #pragma unroll
        for (int q = 0; q < 4; q++) acc[j][q] = 0.f;

    for (int kb = 0; kb < 3; kb++) {
        // copy pre-split X chunk (32 rows x 256 cols, hi+lo) into smem pitch 528
        for (int i = tid; i < 2048; i += 256) {
            const int buf = i >> 10;
            const int e = i & 1023;
            const int r = e >> 5, q = e & 31;
            const __nv_bfloat16* srcb = (buf ? g_Xl : g_Xh) + (size_t)(v0 + r) * 768;
            const uint4 val = *((const uint4*)srcb + kb * 32 + q);
            *(uint4*)(sm + (buf ? SM_XL : SM_XH) + r * HPITCH_B + q * 16) = val;
        }
        __syncthreads();
        for (int kt = 0; kt < 16; kt++) {
            const int g = kb * 16 + kt;
            uint32_t ah[4], al[4];
            const uint32_t addr = smb + SM_XH
                + (uint32_t)(wr * 16 + (lane & 15)) * HPITCH_B
                + ((uint32_t)(lane >> 4)) * 16 + (uint32_t)kt * 32;
            ldmatrix4(ah, addr);
            ldmatrix4(al, addr + (SM_XL - SM_XH));
            const uint2* bh = (const uint2*)g_r0h + ((g * 32 + wc * 8) * 32 + lane);
            const uint2* bl = (const uint2*)g_r0l + ((g * 32 + wc * 8) * 32 + lane);
            #pragma unroll
            for (int j = 0; j < 8; j++) {
                const uint2 Bh = __ldg(bh + j * 32);
                const uint2 Bl = __ldg(bl + j * 32);
                mma16816(acc[j], ah, Bh.x, Bh.y);
                mma16816(acc[j], ah, Bl.x, Bl.y);
                mma16816(acc[j], al, Bh.x, Bh.y);
            }
        }
        __syncthreads();
    }
    // epilogue: lrelu(acc + rhob0) -> split into z1 buffers
    {
        const int r0 = wr * 16 + (lane >> 2);
        #pragma unroll
        for (int j = 0; j < 8; j++) {
            const int c0 = wc * 64 + j * 8 + (lane & 3) * 2;
            const float b0v = __ldg(&rhob0[c0]), b1v = __ldg(&rhob0[c0 + 1]);
            float vv[4] = {lrelu(acc[j][0] + b0v), lrelu(acc[j][1] + b1v),
                           lrelu(acc[j][2] + b0v), lrelu(acc[j][3] + b1v)};
            #pragma unroll
            for (int q = 0; q < 4; q++) {
                const int rr = (q < 2) ? r0 : r0 + 8;
                const int cc = c0 + (q & 1);
                __nv_bfloat16 hi = __float2bfloat16(vv[q]);
                *(__nv_bfloat16*)(sm + SM_Z1H + rr * HPITCH_B + cc * 2) = hi;
                *(__nv_bfloat16*)(sm + SM_Z1L + rr * HPITCH_B + cc * 2) =
                    __float2bfloat16(vv[q] - __bfloat162float(hi));
            }
        }
    }
    __syncthreads();

    // ---- phase 2: agg = z1 @ rhoW1 + rhob1 (K=256) -> split into xa buffers
    #pragma unroll
    for (int j = 0; j < 8; j++)
        #pragma unroll
        for (int q = 0; q < 4; q++) acc[j][q] = 0.f;

    for (int kt = 0; kt < 16; kt++) {
        uint32_t ah[4], al[4];
        const uint32_t addr = smb + SM_Z1H
            + (uint32_t)(wr * 16 + (lane & 15)) * HPITCH_B
            + ((uint32_t)(lane >> 4)) * 16 + (uint32_t)kt * 32;
        ldmatrix4(ah, addr);
        ldmatrix4(al, addr + (SM_Z1L - SM_Z1H));
        const uint2* bh = (const uint2*)g_r1h + ((kt * 32 + wc * 8) * 32 + lane);
        const uint2* bl = (const uint2*)g_r1l + ((kt * 32 + wc * 8) * 32 + lane);
        #pragma unroll
        for (int j = 0; j < 8; j++) {
            const uint2 Bh = __ldg(bh + j * 32);
            const uint2 Bl = __ldg(bl + j * 32);
            mma16816(acc[j], ah, Bh.x, Bh.y);
            mma16816(acc[j], ah, Bl.x, Bl.y);
            mma16816(acc[j], al, Bh.x, Bh.y);
        }
    }
    {
        const int r0 = wr * 16 + (lane >> 2);
        #pragma unroll
        for (int j = 0; j < 8; j++) {
            const int c0 = wc * 64 + j * 8 + (lane & 3) * 2;
            const float b0v = __ldg(&rhob1[c0]), b1v = __ldg(&rhob1[c0 + 1]);
            float vv[4] = {acc[j][0] + b0v, acc[j][1] + b1v,
                           acc[j][2] + b0v, acc[j][3] + b1v};
            #pragma unroll
            for (int q = 0; q < 4; q++) {
                const int rr = (q < 2) ? r0 : r0 + 8;
                const int cc = c0 + (q & 1);
                __nv_bfloat16 hi = __float2bfloat16(vv[q]);
                *(__nv_bfloat16*)(sm + SM_XH + rr * HPITCH_B + cc * 2) = hi;
                *(__nv_bfloat16*)(sm + SM_XL + rr * HPITCH_B + cc * 2) =
                    __float2bfloat16(vv[q] - __bfloat162float(hi));
            }
        }
    }
    __syncthreads();

    // ---- phase 3: per-type out heads
    const float ml = *max_logit;
    for (int t = 0; t < 3; t++) {
        if (tid < 32) logits_s[tid] = 0.f;
        __syncthreads();

        #pragma unroll
        for (int j = 0; j < 8; j++)
            #pragma unroll
            for (int q = 0; q < 4; q++) acc[j][q] = 0.f;

        for (int kt = 0; kt < 16; kt++) {
            uint32_t ah[4], al[4];
            const uint32_t addr = smb + SM_XH
                + (uint32_t)(wr * 16 + (lane & 15)) * HPITCH_B
                + ((uint32_t)(lane >> 4)) * 16 + (uint32_t)kt * 32;
            ldmatrix4(ah, addr);
            ldmatrix4(al, addr + (SM_XL - SM_XH));
            const int g = t * 16 + kt;
            const uint2* bh = (const uint2*)g_oWh + ((g * 32 + wc * 8) * 32 + lane);
            const uint2* bl = (const uint2*)g_oWl + ((g * 32 + wc * 8) * 32 + lane);
            #pragma unroll
            for (int j = 0; j < 8; j++) {
                const uint2 Bh = __ldg(bh + j * 32);
                const uint2 Bl = __ldg(bl + j * 32);
                mma16816(acc[j], ah, Bh.x, Bh.y);
                mma16816(acc[j], ah, Bl.x, Bl.y);
                mma16816(acc[j], al, Bh.x, Bh.y);
            }
        }

        // o = lrelu(acc + b1t); dot with W2t; reduce to logits
        float p0 = 0.f, p1 = 0.f;
        #pragma unroll
        for (int j = 0; j < 8; j++) {
            const int c0 = wc * 64 + j * 8 + (lane & 3) * 2;
            const float bb0 = __ldg(&outb1[t * H + c0]);
            const float bb1 = __ldg(&outb1[t * H + c0 + 1]);
            const float w20 = __ldg(&outW2[t * H + c0]);
            const float w21 = __ldg(&outW2[t * H + c0 + 1]);
            p0 += lrelu(acc[j][0] + bb0) * w20 + lrelu(acc[j][1] + bb1) * w21;
            p1 += lrelu(acc[j][2] + bb0) * w20 + lrelu(acc[j][3] + bb1) * w21;
        }
        p0 += __shfl_xor_sync(0xffffffffu, p0, 1);
        p0 += __shfl_xor_sync(0xffffffffu, p0, 2);
        p1 += __shfl_xor_sync(0xffffffffu, p1, 1);
        p1 += __shfl_xor_sync(0xffffffffu, p1, 2);
        if ((lane & 3) == 0) {
            const int r0 = wr * 16 + (lane >> 2);
            atomicAdd(&logits_s[r0], p0);
            atomicAdd(&logits_s[r0 + 8], p1);
        }
        __syncthreads();
        if (tid < 32) {
            const int v = v0 + tid;
            if (vtypes[v] == t) {
                float l = logits_s[tid] + outb2[t];
                const int ci = min(g_alt_cnt[v], MAX_ALT);
                l *= conf[ci];
                out[v] = ml * tanhf(l / ml);
            }
        }
        __syncthreads();
    }
}

// ---------------- launch ----------------
extern "C" void kernel_launch(void* const* d_in, const int* in_sizes, int n_in,
                              void* d_out, int out_size)
{
    const float* reads  = (const float*)d_in[0];
    const float* info   = (const float*)d_in[1];
    const int*   refseg = (const int*)  d_in[2];
    const int*   altseg = (const int*)  d_in[3];
    const int*   vtypes = (const int*)  d_in[4];
    const float* phiW0  = (const float*)d_in[5];
    const float* phib0  = (const float*)d_in[6];
    const float* phiW1  = (const float*)d_in[7];
    const float* phib1  = (const float*)d_in[8];
    const float* omW0   = (const float*)d_in[9];
    const float* omb0   = (const float*)d_in[10];
    const float* rhoW0  = (const float*)d_in[11];
    const float* rhob0  = (const float*)d_in[12];
    const float* rhoW1  = (const float*)d_in[13];
    const float* rhob1  = (const float*)d_in[14];
    const float* outW1  = (const float*)d_in[15];
    const float* outb1  = (const float*)d_in[16];
    const float* outW2  = (const float*)d_in[17];
    const float* outb2  = (const float*)d_in[18];
    const float* conf   = (const float*)d_in[19];
    const float* maxl   = (const float*)d_in[20];
    float* out = (float*)d_out;

    static uint32_t *pW1h = nullptr, *pW1l, *pr0h, *pr0l, *pr1h, *pr1l, *poWh, *poWl;
    cudaGetSymbolAddress((void**)&pW1h, g_W1hf);
    cudaGetSymbolAddress((void**)&pW1l, g_W1lf);
    cudaGetSymbolAddress((void**)&pr0h, g_r0h);
    cudaGetSymbolAddress((void**)&pr0l, g_r0l);
    cudaGetSymbolAddress((void**)&pr1h, g_r1h);
    cudaGetSymbolAddress((void**)&pr1l, g_r1l);
    cudaGetSymbolAddress((void**)&poWh, g_oWh);
    cudaGetSymbolAddress((void**)&poWl, g_oWl);

    cudaFuncSetAttribute(phi_mma_kernel,  cudaFuncAttributeMaxDynamicSharedMemorySize, PHI_SMEM_TOTAL);
    cudaFuncSetAttribute(head_mma_kernel, cudaFuncAttributeMaxDynamicSharedMemorySize, HEAD_SMEM_TOTAL);

    zero_kernel<<<(V * H + 255) / 256, 256>>>();
    convW_frag<<<64, 256>>>(phiW1, 16, pW1h, pW1l);
    convW_frag<<<192, 256>>>(rhoW0, 48, pr0h, pr0l);
    convW_frag<<<64, 256>>>(rhoW1, 16, pr1h, pr1l);
    convW_frag<<<192, 256>>>(outW1, 48, poWh, poWl);
    phi_mma_kernel<<<(NREF + NALT) / TILE_R, 512, PHI_SMEM_TOTAL>>>(
        reads, refseg, altseg, phiW0, phib0, phib1);
    build_X_kernel<<<V / 8, 256>>>(info, omW0, omb0);
    head_mma_kernel<<<V / 32, 256, HEAD_SMEM_TOTAL>>>(
        vtypes, rhob0, rhob1, outb1, outb2, outW2, conf, maxl, out);
}

// round 7
// speedup vs baseline: 2.3464x; 1.0064x over previous
#include <cuda_runtime.h>
#include <cuda_bf16.h>
#include <math.h>
#include <stdint.h>

#define V     8192
#define NREF  262144
#define NALT  131072
#define FREAD 11
#define FINFO 9
#define H     256
#define MAX_ALT 10

#define TILE_R 128

// ---------------- scratch ----------------
__device__ float g_ref_sums[V * H];
__device__ float g_alt_sums[V * H];
__device__ int   g_ref_cnt[V];
__device__ int   g_alt_cnt[V];
__device__ __align__(16) __nv_bfloat16 g_Xh[V * 768];
__device__ __align__(16) __nv_bfloat16 g_Xl[V * 768];
// weights in mma-fragment-linear order: [kt][nt(32)][lane(32)][reg(2)] uint32
__device__ __align__(16) uint32_t g_W1hf[16 * 2048];
__device__ __align__(16) uint32_t g_W1lf[16 * 2048];
__device__ __align__(16) uint32_t g_r0h[48 * 2048];
__device__ __align__(16) uint32_t g_r0l[48 * 2048];
__device__ __align__(16) uint32_t g_r1h[16 * 2048];
__device__ __align__(16) uint32_t g_r1l[16 * 2048];
__device__ __align__(16) uint32_t g_oWh[48 * 2048];
__device__ __align__(16) uint32_t g_oWl[48 * 2048];

// ---------------- helpers ----------------
__device__ __forceinline__ float lrelu(float x) { return x > 0.f ? x : 0.01f * x; }
__device__ __forceinline__ float sigmoidf_(float x) { return 1.f / (1.f + __expf(-x)); }

__device__ __forceinline__ uint32_t pack_bf16x2(__nv_bfloat16 lo16, __nv_bfloat16 hi16) {
    return ((uint32_t)__bfloat16_as_ushort(hi16) << 16) | (uint32_t)__bfloat16_as_ushort(lo16);
}

__device__ __forceinline__ void mma16816(float* c, const uint32_t* a, uint32_t b0, uint32_t b1) {
    asm volatile(
        "mma.sync.aligned.m16n8k16.row.col.f32.bf16.bf16.f32 "
        "{%0,%1,%2,%3}, {%4,%5,%6,%7}, {%8,%9}, {%0,%1,%2,%3};"
        : "+f"(c[0]), "+f"(c[1]), "+f"(c[2]), "+f"(c[3])
        : "r"(a[0]), "r"(a[1]), "r"(a[2]), "r"(a[3]), "r"(b0), "r"(b1));
}

__device__ __forceinline__ void ldmatrix4(uint32_t* r, uint32_t addr) {
    asm volatile("ldmatrix.sync.aligned.m8n8.x4.shared.b16 {%0,%1,%2,%3}, [%4];"
                 : "=r"(r[0]), "=r"(r[1]), "=r"(r[2]), "=r"(r[3]) : "r"(addr));
}

__device__ __forceinline__ void cpasync16(uint32_t dst_smem, const void* src) {
    asm volatile("cp.async.cg.shared.global [%0], [%1], 16;" :: "r"(dst_smem), "l"(src) : "memory");
}

// ---------------- kernel 0: fused zero + all weight conversions ----------------
// blocks [0, 8192): zero sums/cnt ; blocks [8192, 8704): convert weights
__global__ void prelude_kernel(const float* __restrict__ W1, const float* __restrict__ r0,
                               const float* __restrict__ r1, const float* __restrict__ oW) {
    const int b = blockIdx.x;
    const int tid = threadIdx.x;
    if (b < 8192) {
        const int idx = b * 256 + tid;
        g_ref_sums[idx] = 0.f;
        g_alt_sums[idx] = 0.f;
        if (idx < V) { g_ref_cnt[idx] = 0; g_alt_cnt[idx] = 0; }
        return;
    }
    int cb = b - 8192;
    const float* W;
    uint32_t *dh, *dl;
    if (cb < 64)       { W = W1; dh = g_W1hf; dl = g_W1lf; }
    else if (cb < 256) { W = r0; dh = g_r0h;  dl = g_r0l;  cb -= 64; }
    else if (cb < 320) { W = r1; dh = g_r1h;  dl = g_r1l;  cb -= 256; }
    else               { W = oW; dh = g_oWh;  dl = g_oWl;  cb -= 320; }
    const int idx = cb * 256 + tid;
    const int lane = idx & 31;
    const int nt   = (idx >> 5) & 31;
    const int kt   = idx >> 10;
    const int n = nt * 8 + (lane >> 2);
    const int kbase = kt * 16 + (lane & 3) * 2;
    #pragma unroll
    for (int r = 0; r < 2; r++) {
        const int k = kbase + 8 * r;
        const float w0 = W[k * 256 + n];
        const float w1 = W[(k + 1) * 256 + n];
        __nv_bfloat16 h0 = __float2bfloat16(w0), h1 = __float2bfloat16(w1);
        __nv_bfloat16 l0 = __float2bfloat16(w0 - __bfloat162float(h0));
        __nv_bfloat16 l1 = __float2bfloat16(w1 - __bfloat162float(h1));
        dh[idx * 2 + r] = pack_bf16x2(h0, h1);
        dl[idx * 2 + r] = pack_bf16x2(l0, l1);
    }
}

// ---------------- kernel 1: fused phi MLP + segment reduce (cp.async-staged B) ----------------
#define HPITCH_B 528
#define SM_HSH   0
#define SM_HSL   (128 * HPITCH_B)          // 67584
#define SM_B     (2 * 128 * HPITCH_B)      // 135168 ; 2 buffers x (2 kt x 16KB) = 65536
#define SM_XST   (SM_B + 65536)            // 200704
#define SM_SEGS  (SM_XST + 11 * 128 * 4)   // 206336
#define PHI_SMEM_TOTAL (SM_SEGS + 512)     // 206848
#define YPITCH 257

__global__ __launch_bounds__(512, 1) void phi_mma_kernel(
    const float* __restrict__ reads,
    const int* __restrict__ ref_seg, const int* __restrict__ alt_seg,
    const float* __restrict__ W0, const float* __restrict__ b0,
    const float* __restrict__ b1)
{
    extern __shared__ char sm[];
    const uint32_t smb = (uint32_t)__cvta_generic_to_shared(sm);
    float* xsT  = (float*)(sm + SM_XST);
    int*   segs = (int*)(sm + SM_SEGS);
    float* ys   = (float*)sm;

    const int tid = threadIdx.x;
    const long base = (long)blockIdx.x * TILE_R;
    const bool is_alt = (base >= NREF);
    const int* seg_src = is_alt ? (alt_seg + (base - NREF)) : (ref_seg + base);

    for (int idx = tid; idx < TILE_R * FREAD; idx += 512) {
        int r = idx / FREAD, c = idx % FREAD;
        xsT[c * 128 + r] = reads[(base + r) * FREAD + c];
    }
    if (tid < TILE_R) segs[tid] = seg_src[tid];
    __syncthreads();

    // counts: parallel spread-address atomics (commutative, overlaps with everything below)
    if (tid < TILE_R) {
        int* cnt = is_alt ? g_alt_cnt : g_ref_cnt;
        atomicAdd(&cnt[segs[tid]], 1);
    }

    // stage 1: h = lrelu(x @ W0 + b0) -> bf16 hi/lo in smem
    {
        const int j = tid & 255;
        const int rbase = (tid >> 8) * 64;
        float w[FREAD];
        #pragma unroll
        for (int k = 0; k < FREAD; k++) w[k] = W0[k * H + j];
        const float bb = b0[j];
        for (int r = rbase; r < rbase + 64; r += 4) {
            float a0 = bb, a1 = bb, a2 = bb, a3 = bb;
            #pragma unroll
            for (int k = 0; k < FREAD; k++) {
                const float4 a = *(const float4*)&xsT[k * 128 + r];
                a0 = fmaf(a.x, w[k], a0); a1 = fmaf(a.y, w[k], a1);
                a2 = fmaf(a.z, w[k], a2); a3 = fmaf(a.w, w[k], a3);
            }
            float hv[4] = {lrelu(a0), lrelu(a1), lrelu(a2), lrelu(a3)};
            #pragma unroll
            for (int q = 0; q < 4; q++) {
                __nv_bfloat16 hi = __float2bfloat16(hv[q]);
                __nv_bfloat16 lo = __float2bfloat16(hv[q] - __bfloat162float(hi));
                const int off = (r + q) * HPITCH_B + j * 2;
                *(__nv_bfloat16*)(sm + SM_HSH + off) = hi;
                *(__nv_bfloat16*)(sm + SM_HSL + off) = lo;
            }
        }
    }

    // stage pair 0 (kt 0,1) into slot 0 while stage-1 finishes elsewhere
    // staging: 32 KB per pair -> 4 x 16B per thread
    {
        #pragma unroll
        for (int i = 0; i < 4; i++) {
            const int c = tid + 512 * i;          // 0..2047 16B chunks
            const int kk = c >> 10;               // kt within pair
            const int cc = c & 1023;
            const int part = cc >> 9;             // 0=hi 1=lo
            const int e = cc & 511;
            const uint4* src = (const uint4*)(part ? g_W1lf : g_W1hf) + (kk * 512 + e);
            cpasync16(smb + SM_B + kk * 16384 + part * 8192 + e * 16, src);
        }
        asm volatile("cp.async.commit_group;" ::: "memory");
    }
    __syncthreads();   // stage-1 h complete (also covers staging ordering)

    // stage 2: D = h @ W1 via mma.sync, 3-term bf16 split, pipelined B
    const int wid = tid >> 5, lane = tid & 31;
    const int wr = wid >> 2, wc = wid & 3;
    const int rowbase = wr * 32;

    float acc[2][8][4];
    #pragma unroll
    for (int mt = 0; mt < 2; mt++)
        #pragma unroll
        for (int j = 0; j < 8; j++)
            #pragma unroll
            for (int q = 0; q < 4; q++) acc[mt][j][q] = 0.f;

    for (int p = 0; p < 8; p++) {
        if (p < 7) {
            const int s = (p + 1) & 1;
            #pragma unroll
            for (int i = 0; i < 4; i++) {
                const int c = tid + 512 * i;
                const int kk = c >> 10;
                const int cc = c & 1023;
                const int part = cc >> 9;
                const int e = cc & 511;
                const uint4* src = (const uint4*)(part ? g_W1lf : g_W1hf)
                                 + ((2 * (p + 1) + kk) * 512 + e);
                cpasync16(smb + SM_B + s * 32768 + kk * 16384 + part * 8192 + e * 16, src);
            }
            asm volatile("cp.async.commit_group;" ::: "memory");
            asm volatile("cp.async.wait_group 1;" ::: "memory");
        } else {
            asm volatile("cp.async.wait_group 0;" ::: "memory");
        }
        __syncthreads();

        #pragma unroll
        for (int kk = 0; kk < 2; kk++) {
            const int kt = 2 * p + kk;
            uint32_t ah[2][4], al[2][4];
            #pragma unroll
            for (int mt = 0; mt < 2; mt++) {
                const uint32_t addr = smb + SM_HSH
                    + (uint32_t)(rowbase + mt * 16 + (lane & 15)) * HPITCH_B
                    + ((uint32_t)(lane >> 4)) * 16 + (uint32_t)kt * 32;
                ldmatrix4(ah[mt], addr);
                ldmatrix4(al[mt], addr + (SM_HSL - SM_HSH));
            }
            const char* bbase = sm + SM_B + (p & 1) * 32768 + kk * 16384;
            #pragma unroll
            for (int j = 0; j < 8; j++) {
                const int fo = ((wc * 8 + j) * 32 + lane) * 8;
                const uint2 Bh = *(const uint2*)(bbase + fo);
                const uint2 Bl = *(const uint2*)(bbase + 8192 + fo);
                #pragma unroll
                for (int mt = 0; mt < 2; mt++) {
                    mma16816(acc[mt][j], ah[mt], Bh.x, Bh.y);
                    mma16816(acc[mt][j], ah[mt], Bl.x, Bl.y);
                    mma16816(acc[mt][j], al[mt], Bh.x, Bh.y);
                }
            }
        }
        __syncthreads();   // all consumed before next stage overwrites this slot
    }

    // epilogue: bias + sigmoid -> ys[128][257]
    {
        const int colb = wc * 64 + 2 * (lane & 3);
        float bias0[8], bias1[8];
        #pragma unroll
        for (int j = 0; j < 8; j++) {
            bias0[j] = __ldg(&b1[colb + j * 8]);
            bias1[j] = __ldg(&b1[colb + j * 8 + 1]);
        }
        #pragma unroll
        for (int mt = 0; mt < 2; mt++) {
            const int row = rowbase + mt * 16 + (lane >> 2);
            #pragma unroll
            for (int j = 0; j < 8; j++) {
                const int col = colb + j * 8;
                ys[row * YPITCH + col]           = sigmoidf_(acc[mt][j][0] + bias0[j]);
                ys[row * YPITCH + col + 1]       = sigmoidf_(acc[mt][j][1] + bias1[j]);
                ys[(row + 8) * YPITCH + col]     = sigmoidf_(acc[mt][j][2] + bias0[j]);
                ys[(row + 8) * YPITCH + col + 1] = sigmoidf_(acc[mt][j][3] + bias1[j]);
            }
        }
    }
    __syncthreads();

    // sorted-run segment reduction: 2 threads per column (row halves)
    {
        float* sums = is_alt ? g_alt_sums : g_ref_sums;
        const int c = tid & 255;
        const int r0 = (tid >> 8) * 64;
        int cur = segs[r0];
        float a = 0.f;
        #pragma unroll 4
        for (int r = r0; r < r0 + 64; r++) {
            int s = segs[r];
            if (s != cur) { atomicAdd(&sums[cur * H + c], a); a = 0.f; cur = s; }
            a += ys[r * YPITCH + c];
        }
        atomicAdd(&sums[cur * H + c], a);
    }
}

// ---------------- kernel 2: build split X ----------------
__global__ __launch_bounds__(256) void build_X_kernel(
    const float* __restrict__ info,
    const float* __restrict__ omW0, const float* __restrict__ omb0)
{
    const int c = threadIdx.x;
    const int v0 = blockIdx.x * 8;
    float w[FINFO];
    #pragma unroll
    for (int k = 0; k < FINFO; k++) w[k] = omW0[k * H + c];
    const float bb = omb0[c];
    for (int vl = 0; vl < 8; vl++) {
        const int v = v0 + vl;
        const float rc = (float)max(g_ref_cnt[v], 1);
        const float ac = (float)max(g_alt_cnt[v], 1);
        float vals[3];
        vals[0] = g_ref_sums[v * H + c] / rc;
        vals[1] = g_alt_sums[v * H + c] / ac;
        float z = bb;
        #pragma unroll
        for (int k = 0; k < FINFO; k++) z = fmaf(__ldg(&info[v * FINFO + k]), w[k], z);
        vals[2] = sigmoidf_(z);
        #pragma unroll
        for (int p = 0; p < 3; p++) {
            const int idx = v * 768 + p * 256 + c;
            __nv_bfloat16 hi = __float2bfloat16(vals[p]);
            g_Xh[idx] = hi;
            g_Xl[idx] = __float2bfloat16(vals[p] - __bfloat162float(hi));
        }
    }
}

// ---------------- kernel 3: rho MLP + per-type heads (mma.sync bf16 split) ----------------
#define SM_XH   0
#define SM_XL   16896
#define SM_Z1H  33792
#define SM_Z1L  50688
#define SM_LOG  67584
#define HEAD_SMEM_TOTAL 67840

__global__ __launch_bounds__(256, 2) void head_mma_kernel(
    const int* __restrict__ vtypes,
    const float* __restrict__ rhob0, const float* __restrict__ rhob1,
    const float* __restrict__ outb1, const float* __restrict__ outb2,
    const float* __restrict__ outW2,
    const float* __restrict__ conf,  const float* __restrict__ max_logit,
    float* __restrict__ out)
{
    extern __shared__ char sm[];
    const uint32_t smb = (uint32_t)__cvta_generic_to_shared(sm);
    float* logits_s = (float*)(sm + SM_LOG);

    const int tid = threadIdx.x;
    const int wid = tid >> 5, lane = tid & 31;
    const int wr = wid >> 2, wc = wid & 3;
    const int v0 = blockIdx.x * 32;

    float acc[8][4];

    // ---- phase 1: z1 = lrelu(X @ rhoW0 + rhob0), K = 768 in 3 chunks of 256
    #pragma unroll
    for (int j = 0; j < 8; j++)
        #pragma unroll
        for (int q = 0; q < 4; q++) acc[j][q] = 0.f;

    for (int kb = 0; kb < 3; kb++) {
        for (int i = tid; i < 2048; i += 256) {
            const int buf = i >> 10;
            const int e = i & 1023;
            const int r = e >> 5, q = e & 31;
            const __nv_bfloat16* srcb = (buf ? g_Xl : g_Xh) + (size_t)(v0 + r) * 768;
            const uint4 val = *((const uint4*)srcb + kb * 32 + q);
            *(uint4*)(sm + (buf ? SM_XL : SM_XH) + r * HPITCH_B + q * 16) = val;
        }
        __syncthreads();
        for (int kt = 0; kt < 16; kt++) {
            const int g = kb * 16 + kt;
            uint32_t ah[4], al[4];
            const uint32_t addr = smb + SM_XH
                + (uint32_t)(wr * 16 + (lane & 15)) * HPITCH_B
                + ((uint32_t)(lane >> 4)) * 16 + (uint32_t)kt * 32;
            ldmatrix4(ah, addr);
            ldmatrix4(al, addr + (SM_XL - SM_XH));
            const uint2* bh = (const uint2*)g_r0h + ((g * 32 + wc * 8) * 32 + lane);
            const uint2* bl = (const uint2*)g_r0l + ((g * 32 + wc * 8) * 32 + lane);
            #pragma unroll
            for (int j = 0; j < 8; j++) {
                const uint2 Bh = __ldg(bh + j * 32);
                const uint2 Bl = __ldg(bl + j * 32);
                mma16816(acc[j], ah, Bh.x, Bh.y);
                mma16816(acc[j], ah, Bl.x, Bl.y);
                mma16816(acc[j], al, Bh.x, Bh.y);
            }
        }
        __syncthreads();
    }
    {
        const int r0 = wr * 16 + (lane >> 2);
        #pragma unroll
        for (int j = 0; j < 8; j++) {
            const int c0 = wc * 64 + j * 8 + (lane & 3) * 2;
            const float b0v = __ldg(&rhob0[c0]), b1v = __ldg(&rhob0[c0 + 1]);
            float vv[4] = {lrelu(acc[j][0] + b0v), lrelu(acc[j][1] + b1v),
                           lrelu(acc[j][2] + b0v), lrelu(acc[j][3] + b1v)};
            #pragma unroll
            for (int q = 0; q < 4; q++) {
                const int rr = (q < 2) ? r0 : r0 + 8;
                const int cc = c0 + (q & 1);
                __nv_bfloat16 hi = __float2bfloat16(vv[q]);
                *(__nv_bfloat16*)(sm + SM_Z1H + rr * HPITCH_B + cc * 2) = hi;
                *(__nv_bfloat16*)(sm + SM_Z1L + rr * HPITCH_B + cc * 2) =
                    __float2bfloat16(vv[q] - __bfloat162float(hi));
            }
        }
    }
    __syncthreads();

    // ---- phase 2: agg = z1 @ rhoW1 + rhob1 (K=256)
    #pragma unroll
    for (int j = 0; j < 8; j++)
        #pragma unroll
        for (int q = 0; q < 4; q++) acc[j][q] = 0.f;

    for (int kt = 0; kt < 16; kt++) {
        uint32_t ah[4], al[4];
        const uint32_t addr = smb + SM_Z1H
            + (uint32_t)(wr * 16 + (lane & 15)) * HPITCH_B
            + ((uint32_t)(lane >> 4)) * 16 + (uint32_t)kt * 32;
        ldmatrix4(ah, addr);
        ldmatrix4(al, addr + (SM_Z1L - SM_Z1H));
        const uint2* bh = (const uint2*)g_r1h + ((kt * 32 + wc * 8) * 32 + lane);
        const uint2* bl = (const uint2*)g_r1l + ((kt * 32 + wc * 8) * 32 + lane);
        #pragma unroll
        for (int j = 0; j < 8; j++) {
            const uint2 Bh = __ldg(bh + j * 32);
            const uint2 Bl = __ldg(bl + j * 32);
            mma16816(acc[j], ah, Bh.x, Bh.y);
            mma16816(acc[j], ah, Bl.x, Bl.y);
            mma16816(acc[j], al, Bh.x, Bh.y);
        }
    }
    {
        const int r0 = wr * 16 + (lane >> 2);
        #pragma unroll
        for (int j = 0; j < 8; j++) {
            const int c0 = wc * 64 + j * 8 + (lane & 3) * 2;
            const float b0v = __ldg(&rhob1[c0]), b1v = __ldg(&rhob1[c0 + 1]);
            float vv[4] = {acc[j][0] + b0v, acc[j][1] + b1v,
                           acc[j][2] + b0v, acc[j][3] + b1v};
            #pragma unroll
            for (int q = 0; q < 4; q++) {
                const int rr = (q < 2) ? r0 : r0 + 8;
                const int cc = c0 + (q & 1);
                __nv_bfloat16 hi = __float2bfloat16(vv[q]);
                *(__nv_bfloat16*)(sm + SM_XH + rr * HPITCH_B + cc * 2) = hi;
                *(__nv_bfloat16*)(sm + SM_XL + rr * HPITCH_B + cc * 2) =
                    __float2bfloat16(vv[q] - __bfloat162float(hi));
            }
        }
    }
    __syncthreads();

    // ---- phase 3: per-type out heads
    const float ml = *max_logit;
    for (int t = 0; t < 3; t++) {
        if (tid < 32) logits_s[tid] = 0.f;
        __syncthreads();

        #pragma unroll
        for (int j = 0; j < 8; j++)
            #pragma unroll
            for (int q = 0; q < 4; q++) acc[j][q] = 0.f;

        for (int kt = 0; kt < 16; kt++) {
            uint32_t ah[4], al[4];
            const uint32_t addr = smb + SM_XH
                + (uint32_t)(wr * 16 + (lane & 15)) * HPITCH_B
                + ((uint32_t)(lane >> 4)) * 16 + (uint32_t)kt * 32;
            ldmatrix4(ah, addr);
            ldmatrix4(al, addr + (SM_XL - SM_XH));
            const int g = t * 16 + kt;
            const uint2* bh = (const uint2*)g_oWh + ((g * 32 + wc * 8) * 32 + lane);
            const uint2* bl = (const uint2*)g_oWl + ((g * 32 + wc * 8) * 32 + lane);
            #pragma unroll
            for (int j = 0; j < 8; j++) {
                const uint2 Bh = __ldg(bh + j * 32);
                const uint2 Bl = __ldg(bl + j * 32);
                mma16816(acc[j], ah, Bh.x, Bh.y);
                mma16816(acc[j], ah, Bl.x, Bl.y);
                mma16816(acc[j], al, Bh.x, Bh.y);
            }
        }

        float p0 = 0.f, p1 = 0.f;
        #pragma unroll
        for (int j = 0; j < 8; j++) {
            const int c0 = wc * 64 + j * 8 + (lane & 3) * 2;
            const float bb0 = __ldg(&outb1[t * H + c0]);
            const float bb1 = __ldg(&outb1[t * H + c0 + 1]);
            const float w20 = __ldg(&outW2[t * H + c0]);
            const float w21 = __ldg(&outW2[t * H + c0 + 1]);
            p0 += lrelu(acc[j][0] + bb0) * w20 + lrelu(acc[j][1] + bb1) * w21;
            p1 += lrelu(acc[j][2] + bb0) * w20 + lrelu(acc[j][3] + bb1) * w21;
        }
        p0 += __shfl_xor_sync(0xffffffffu, p0, 1);
        p0 += __shfl_xor_sync(0xffffffffu, p0, 2);
        p1 += __shfl_xor_sync(0xffffffffu, p1, 1);
        p1 += __shfl_xor_sync(0xffffffffu, p1, 2);
        if ((lane & 3) == 0) {
            const int r0 = wr * 16 + (lane >> 2);
            atomicAdd(&logits_s[r0], p0);
            atomicAdd(&logits_s[r0 + 8], p1);
        }
        __syncthreads();
        if (tid < 32) {
            const int v = v0 + tid;
            if (vtypes[v] == t) {
                float l = logits_s[tid] + outb2[t];
                const int ci = min(g_alt_cnt[v], MAX_ALT);
                l *= conf[ci];
                out[v] = ml * tanhf(l / ml);
            }
        }
        __syncthreads();
    }
}

// ---------------- launch ----------------
extern "C" void kernel_launch(void* const* d_in, const int* in_sizes, int n_in,
                              void* d_out, int out_size)
{
    const float* reads  = (const float*)d_in[0];
    const float* info   = (const float*)d_in[1];
    const int*   refseg = (const int*)  d_in[2];
    const int*   altseg = (const int*)  d_in[3];
    const int*   vtypes = (const int*)  d_in[4];
    const float* phiW0  = (const float*)d_in[5];
    const float* phib0  = (const float*)d_in[6];
    const float* phiW1  = (const float*)d_in[7];
    const float* phib1  = (const float*)d_in[8];
    const float* omW0   = (const float*)d_in[9];
    const float* omb0   = (const float*)d_in[10];
    const float* rhoW0  = (const float*)d_in[11];
    const float* rhob0  = (const float*)d_in[12];
    const float* rhoW1  = (const float*)d_in[13];
    const float* rhob1  = (const float*)d_in[14];
    const float* outW1  = (const float*)d_in[15];
    const float* outb1  = (const float*)d_in[16];
    const float* outW2  = (const float*)d_in[17];
    const float* outb2  = (const float*)d_in[18];
    const float* conf   = (const float*)d_in[19];
    const float* maxl   = (const float*)d_in[20];
    float* out = (float*)d_out;

    cudaFuncSetAttribute(phi_mma_kernel,  cudaFuncAttributeMaxDynamicSharedMemorySize, PHI_SMEM_TOTAL);
    cudaFuncSetAttribute(head_mma_kernel, cudaFuncAttributeMaxDynamicSharedMemorySize, HEAD_SMEM_TOTAL);

    prelude_kernel<<<8704, 256>>>(phiW1, rhoW0, rhoW1, outW1);
    phi_mma_kernel<<<(NREF + NALT) / TILE_R, 512, PHI_SMEM_TOTAL>>>(
        reads, refseg, altseg, phiW0, phib0, phib1);
    build_X_kernel<<<V / 8, 256>>>(info, omW0, omb0);
    head_mma_kernel<<<V / 32, 256, HEAD_SMEM_TOTAL>>>(
        vtypes, rhob0, rhob1, outb1, outb2, outW2, conf, maxl, out);
}

// round 8
// speedup vs baseline: 2.9824x; 1.2711x over previous
#include <cuda_runtime.h>
#include <cuda_bf16.h>
#include <math.h>
#include <stdint.h>

#define V     8192
#define NREF  262144
#define NALT  131072
#define FREAD 11
#define FINFO 9
#define H     256
#define MAX_ALT 10

#define TILE_R 64

// ---------------- scratch ----------------
__device__ float g_ref_sums[V * H];
__device__ float g_alt_sums[V * H];
__device__ int   g_ref_cnt[V];
__device__ int   g_alt_cnt[V];
__device__ __align__(16) __nv_bfloat16 g_Xh[V * 768];
__device__ __align__(16) __nv_bfloat16 g_Xl[V * 768];
// weights, interleaved mma fragments: uint4 {hi_r0, hi_r1, lo_r0, lo_r1} per [kt][nt(32)][lane(32)]
__device__ __align__(16) uint4 g_W1i[16 * 1024];
__device__ __align__(16) uint4 g_r0i[48 * 1024];
__device__ __align__(16) uint4 g_r1i[16 * 1024];
__device__ __align__(16) uint4 g_oWi[48 * 1024];

// ---------------- helpers ----------------
__device__ __forceinline__ float lrelu(float x) { return x > 0.f ? x : 0.01f * x; }
__device__ __forceinline__ float sigmoidf_(float x) { return 1.f / (1.f + __expf(-x)); }

__device__ __forceinline__ uint32_t pack_bf16x2(__nv_bfloat16 lo16, __nv_bfloat16 hi16) {
    return ((uint32_t)__bfloat16_as_ushort(hi16) << 16) | (uint32_t)__bfloat16_as_ushort(lo16);
}

__device__ __forceinline__ void mma16816(float* c, const uint32_t* a, uint32_t b0, uint32_t b1) {
    asm volatile(
        "mma.sync.aligned.m16n8k16.row.col.f32.bf16.bf16.f32 "
        "{%0,%1,%2,%3}, {%4,%5,%6,%7}, {%8,%9}, {%0,%1,%2,%3};"
        : "+f"(c[0]), "+f"(c[1]), "+f"(c[2]), "+f"(c[3])
        : "r"(a[0]), "r"(a[1]), "r"(a[2]), "r"(a[3]), "r"(b0), "r"(b1));
}

__device__ __forceinline__ void ldmatrix4(uint32_t* r, uint32_t addr) {
    asm volatile("ldmatrix.sync.aligned.m8n8.x4.shared.b16 {%0,%1,%2,%3}, [%4];"
                 : "=r"(r[0]), "=r"(r[1]), "=r"(r[2]), "=r"(r[3]) : "r"(addr));
}

// ---------------- kernel 0: fused zero + all weight conversions ----------------
__global__ void prelude_kernel(const float* __restrict__ W1, const float* __restrict__ r0,
                               const float* __restrict__ r1, const float* __restrict__ oW) {
    const int b = blockIdx.x;
    const int tid = threadIdx.x;
    if (b < 8192) {
        const int idx = b * 256 + tid;
        g_ref_sums[idx] = 0.f;
        g_alt_sums[idx] = 0.f;
        if (idx < V) { g_ref_cnt[idx] = 0; g_alt_cnt[idx] = 0; }
        return;
    }
    int cb = b - 8192;
    const float* W;
    uint4* dst;
    if (cb < 64)       { W = W1; dst = g_W1i; }
    else if (cb < 256) { W = r0; dst = g_r0i; cb -= 64; }
    else if (cb < 320) { W = r1; dst = g_r1i; cb -= 256; }
    else               { W = oW; dst = g_oWi; cb -= 320; }
    const int idx = cb * 256 + tid;
    const int lane = idx & 31;
    const int nt   = (idx >> 5) & 31;
    const int kt   = idx >> 10;
    const int n = nt * 8 + (lane >> 2);
    const int kbase = kt * 16 + (lane & 3) * 2;
    uint32_t hv[2], lv[2];
    #pragma unroll
    for (int r = 0; r < 2; r++) {
        const int k = kbase + 8 * r;
        const float w0 = W[k * 256 + n];
        const float w1 = W[(k + 1) * 256 + n];
        __nv_bfloat16 h0 = __float2bfloat16(w0), h1 = __float2bfloat16(w1);
        __nv_bfloat16 l0 = __float2bfloat16(w0 - __bfloat162float(h0));
        __nv_bfloat16 l1 = __float2bfloat16(w1 - __bfloat162float(h1));
        hv[r] = pack_bf16x2(h0, h1);
        lv[r] = pack_bf16x2(l0, l1);
    }
    dst[idx] = make_uint4(hv[0], hv[1], lv[0], lv[1]);
}

// ---------------- kernel 1: fused phi MLP + segment reduce (64 rows, 2 blocks/SM) ----------------
#define HPITCH_B 528
#define SM_HSH   0
#define SM_HSL   (TILE_R * HPITCH_B)               // 33792
#define SM_XST   (2 * TILE_R * HPITCH_B)           // 67584
#define SM_SEGS  (SM_XST + FREAD * TILE_R * 4)     // 70400
#define PHI_SMEM_TOTAL (SM_SEGS + 512)             // 70912
#define YPITCH 257

__global__ __launch_bounds__(256, 2) void phi_mma_kernel(
    const float* __restrict__ reads,
    const int* __restrict__ ref_seg, const int* __restrict__ alt_seg,
    const float* __restrict__ W0, const float* __restrict__ b0,
    const float* __restrict__ b1)
{
    extern __shared__ char sm[];
    const uint32_t smb = (uint32_t)__cvta_generic_to_shared(sm);
    float* xsT  = (float*)(sm + SM_XST);
    int*   segs = (int*)(sm + SM_SEGS);
    float* ys   = (float*)sm;

    const int tid = threadIdx.x;
    const long base = (long)blockIdx.x * TILE_R;
    const bool is_alt = (base >= NREF);
    const int* seg_src = is_alt ? (alt_seg + (base - NREF)) : (ref_seg + base);

    for (int idx = tid; idx < TILE_R * FREAD; idx += 256) {
        int r = idx / FREAD, c = idx % FREAD;
        xsT[c * TILE_R + r] = reads[(base + r) * FREAD + c];
    }
    if (tid < TILE_R) segs[tid] = seg_src[tid];
    __syncthreads();

    // counts: parallel spread-address atomics
    if (tid < TILE_R) {
        int* cnt = is_alt ? g_alt_cnt : g_ref_cnt;
        atomicAdd(&cnt[segs[tid]], 1);
    }

    // stage 1: h = lrelu(x @ W0 + b0) -> bf16 hi/lo in smem (thread = column)
    {
        const int j = tid;
        float w[FREAD];
        #pragma unroll
        for (int k = 0; k < FREAD; k++) w[k] = W0[k * H + j];
        const float bb = b0[j];
        for (int r = 0; r < TILE_R; r += 4) {
            float a0 = bb, a1 = bb, a2 = bb, a3 = bb;
            #pragma unroll
            for (int k = 0; k < FREAD; k++) {
                const float4 a = *(const float4*)&xsT[k * TILE_R + r];
                a0 = fmaf(a.x, w[k], a0); a1 = fmaf(a.y, w[k], a1);
                a2 = fmaf(a.z, w[k], a2); a3 = fmaf(a.w, w[k], a3);
            }
            float hv[4] = {lrelu(a0), lrelu(a1), lrelu(a2), lrelu(a3)};
            #pragma unroll
            for (int q = 0; q < 4; q++) {
                __nv_bfloat16 hi = __float2bfloat16(hv[q]);
                __nv_bfloat16 lo = __float2bfloat16(hv[q] - __bfloat162float(hi));
                const int off = (r + q) * HPITCH_B + j * 2;
                *(__nv_bfloat16*)(sm + SM_HSH + off) = hi;
                *(__nv_bfloat16*)(sm + SM_HSL + off) = lo;
            }
        }
    }
    __syncthreads();

    // stage 2: D[64][256] = h @ W1, 3-term bf16 split, 8 warps (2 row x 4 col)
    const int wid = tid >> 5, lane = tid & 31;
    const int wr = wid >> 2, wc = wid & 3;
    const int rowbase = wr * 32;

    float acc[2][8][4];
    #pragma unroll
    for (int mt = 0; mt < 2; mt++)
        #pragma unroll
        for (int j = 0; j < 8; j++)
            #pragma unroll
            for (int q = 0; q < 4; q++) acc[mt][j][q] = 0.f;

    for (int kt = 0; kt < 16; kt++) {
        uint32_t ah[2][4], al[2][4];
        #pragma unroll
        for (int mt = 0; mt < 2; mt++) {
            const uint32_t addr = smb + SM_HSH
                + (uint32_t)(rowbase + mt * 16 + (lane & 15)) * HPITCH_B
                + ((uint32_t)(lane >> 4)) * 16 + (uint32_t)kt * 32;
            ldmatrix4(ah[mt], addr);
            ldmatrix4(al[mt], addr + (SM_HSL - SM_HSH));
        }
        #pragma unroll
        for (int jh = 0; jh < 2; jh++) {
            uint4 Bv[4];
            #pragma unroll
            for (int jj = 0; jj < 4; jj++)
                Bv[jj] = __ldg(&g_W1i[kt * 1024 + ((wc * 8 + jh * 4 + jj) * 32 + lane)]);
            #pragma unroll
            for (int jj = 0; jj < 4; jj++) {
                const int j = jh * 4 + jj;
                #pragma unroll
                for (int mt = 0; mt < 2; mt++) {
                    mma16816(acc[mt][j], ah[mt], Bv[jj].x, Bv[jj].y);
                    mma16816(acc[mt][j], ah[mt], Bv[jj].z, Bv[jj].w);
                    mma16816(acc[mt][j], al[mt], Bv[jj].x, Bv[jj].y);
                }
            }
        }
    }
    __syncthreads();

    // epilogue: bias + sigmoid -> ys[64][257]
    {
        const int colb = wc * 64 + 2 * (lane & 3);
        float bias0[8], bias1[8];
        #pragma unroll
        for (int j = 0; j < 8; j++) {
            bias0[j] = __ldg(&b1[colb + j * 8]);
            bias1[j] = __ldg(&b1[colb + j * 8 + 1]);
        }
        #pragma unroll
        for (int mt = 0; mt < 2; mt++) {
            const int row = rowbase + mt * 16 + (lane >> 2);
            #pragma unroll
            for (int j = 0; j < 8; j++) {
                const int col = colb + j * 8;
                ys[row * YPITCH + col]           = sigmoidf_(acc[mt][j][0] + bias0[j]);
                ys[row * YPITCH + col + 1]       = sigmoidf_(acc[mt][j][1] + bias1[j]);
                ys[(row + 8) * YPITCH + col]     = sigmoidf_(acc[mt][j][2] + bias0[j]);
                ys[(row + 8) * YPITCH + col + 1] = sigmoidf_(acc[mt][j][3] + bias1[j]);
            }
        }
    }
    __syncthreads();

    // sorted-run segment reduction: thread = column
    {
        float* sums = is_alt ? g_alt_sums : g_ref_sums;
        const int c = tid;
        int cur = segs[0];
        float a = 0.f;
        #pragma unroll 4
        for (int r = 0; r < TILE_R; r++) {
            int s = segs[r];
            if (s != cur) { atomicAdd(&sums[cur * H + c], a); a = 0.f; cur = s; }
            a += ys[r * YPITCH + c];
        }
        atomicAdd(&sums[cur * H + c], a);
    }
}

// ---------------- kernel 2: build split X ----------------
__global__ __launch_bounds__(256) void build_X_kernel(
    const float* __restrict__ info,
    const float* __restrict__ omW0, const float* __restrict__ omb0)
{
    const int c = threadIdx.x;
    const int v0 = blockIdx.x * 8;
    float w[FINFO];
    #pragma unroll
    for (int k = 0; k < FINFO; k++) w[k] = omW0[k * H + c];
    const float bb = omb0[c];
    for (int vl = 0; vl < 8; vl++) {
        const int v = v0 + vl;
        const float rc = (float)max(g_ref_cnt[v], 1);
        const float ac = (float)max(g_alt_cnt[v], 1);
        float vals[3];
        vals[0] = g_ref_sums[v * H + c] / rc;
        vals[1] = g_alt_sums[v * H + c] / ac;
        float z = bb;
        #pragma unroll
        for (int k = 0; k < FINFO; k++) z = fmaf(__ldg(&info[v * FINFO + k]), w[k], z);
        vals[2] = sigmoidf_(z);
        #pragma unroll
        for (int p = 0; p < 3; p++) {
            const int idx = v * 768 + p * 256 + c;
            __nv_bfloat16 hi = __float2bfloat16(vals[p]);
            g_Xh[idx] = hi;
            g_Xl[idx] = __float2bfloat16(vals[p] - __bfloat162float(hi));
        }
    }
}

// ---------------- kernel 3: rho MLP + per-type heads ----------------
#define SM_XH   0
#define SM_XL   16896
#define SM_Z1H  33792
#define SM_Z1L  50688
#define SM_LOG  67584
#define HEAD_SMEM_TOTAL 67840

__global__ __launch_bounds__(256, 2) void head_mma_kernel(
    const int* __restrict__ vtypes,
    const float* __restrict__ rhob0, const float* __restrict__ rhob1,
    const float* __restrict__ outb1, const float* __restrict__ outb2,
    const float* __restrict__ outW2,
    const float* __restrict__ conf,  const float* __restrict__ max_logit,
    float* __restrict__ out)
{
    extern __shared__ char sm[];
    const uint32_t smb = (uint32_t)__cvta_generic_to_shared(sm);
    float* logits_s = (float*)(sm + SM_LOG);

    const int tid = threadIdx.x;
    const int wid = tid >> 5, lane = tid & 31;
    const int wr = wid >> 2, wc = wid & 3;
    const int v0 = blockIdx.x * 32;

    float acc[8][4];

    // ---- phase 1: z1 = lrelu(X @ rhoW0 + rhob0), K = 768 in 3 chunks of 256
    #pragma unroll
    for (int j = 0; j < 8; j++)
        #pragma unroll
        for (int q = 0; q < 4; q++) acc[j][q] = 0.f;

    for (int kb = 0; kb < 3; kb++) {
        for (int i = tid; i < 2048; i += 256) {
            const int buf = i >> 10;
            const int e = i & 1023;
            const int r = e >> 5, q = e & 31;
            const __nv_bfloat16* srcb = (buf ? g_Xl : g_Xh) + (size_t)(v0 + r) * 768;
            const uint4 val = *((const uint4*)srcb + kb * 32 + q);
            *(uint4*)(sm + (buf ? SM_XL : SM_XH) + r * HPITCH_B + q * 16) = val;
        }
        __syncthreads();
        for (int kt = 0; kt < 16; kt++) {
            const int g = kb * 16 + kt;
            uint32_t ah[4], al[4];
            const uint32_t addr = smb + SM_XH
                + (uint32_t)(wr * 16 + (lane & 15)) * HPITCH_B
                + ((uint32_t)(lane >> 4)) * 16 + (uint32_t)kt * 32;
            ldmatrix4(ah, addr);
            ldmatrix4(al, addr + (SM_XL - SM_XH));
            #pragma unroll
            for (int j = 0; j < 8; j++) {
                const uint4 B = __ldg(&g_r0i[g * 1024 + ((wc * 8 + j) * 32 + lane)]);
                mma16816(acc[j], ah, B.x, B.y);
                mma16816(acc[j], ah, B.z, B.w);
                mma16816(acc[j], al, B.x, B.y);
            }
        }
        __syncthreads();
    }
    {
        const int r0 = wr * 16 + (lane >> 2);
        #pragma unroll
        for (int j = 0; j < 8; j++) {
            const int c0 = wc * 64 + j * 8 + (lane & 3) * 2;
            const float b0v = __ldg(&rhob0[c0]), b1v = __ldg(&rhob0[c0 + 1]);
            float vv[4] = {lrelu(acc[j][0] + b0v), lrelu(acc[j][1] + b1v),
                           lrelu(acc[j][2] + b0v), lrelu(acc[j][3] + b1v)};
            #pragma unroll
            for (int q = 0; q < 4; q++) {
                const int rr = (q < 2) ? r0 : r0 + 8;
                const int cc = c0 + (q & 1);
                __nv_bfloat16 hi = __float2bfloat16(vv[q]);
                *(__nv_bfloat16*)(sm + SM_Z1H + rr * HPITCH_B + cc * 2) = hi;
                *(__nv_bfloat16*)(sm + SM_Z1L + rr * HPITCH_B + cc * 2) =
                    __float2bfloat16(vv[q] - __bfloat162float(hi));
            }
        }
    }
    __syncthreads();

    // ---- phase 2: agg = z1 @ rhoW1 + rhob1 (K=256)
    #pragma unroll
    for (int j = 0; j < 8; j++)
        #pragma unroll
        for (int q = 0; q < 4; q++) acc[j][q] = 0.f;

    for (int kt = 0; kt < 16; kt++) {
        uint32_t ah[4], al[4];
        const uint32_t addr = smb + SM_Z1H
            + (uint32_t)(wr * 16 + (lane & 15)) * HPITCH_B
            + ((uint32_t)(lane >> 4)) * 16 + (uint32_t)kt * 32;
        ldmatrix4(ah, addr);
        ldmatrix4(al, addr + (SM_Z1L - SM_Z1H));
        #pragma unroll
        for (int j = 0; j < 8; j++) {
            const uint4 B = __ldg(&g_r1i[kt * 1024 + ((wc * 8 + j) * 32 + lane)]);
            mma16816(acc[j], ah, B.x, B.y);
            mma16816(acc[j], ah, B.z, B.w);
            mma16816(acc[j], al, B.x, B.y);
        }
    }
    {
        const int r0 = wr * 16 + (lane >> 2);
        #pragma unroll
        for (int j = 0; j < 8; j++) {
            const int c0 = wc * 64 + j * 8 + (lane & 3) * 2;
            const float b0v = __ldg(&rhob1[c0]), b1v = __ldg(&rhob1[c0 + 1]);
            float vv[4] = {acc[j][0] + b0v, acc[j][1] + b1v,
                           acc[j][2] + b0v, acc[j][3] + b1v};
            #pragma unroll
            for (int q = 0; q < 4; q++) {
                const int rr = (q < 2) ? r0 : r0 + 8;
                const int cc = c0 + (q & 1);
                __nv_bfloat16 hi = __float2bfloat16(vv[q]);
                *(__nv_bfloat16*)(sm + SM_XH + rr * HPITCH_B + cc * 2) = hi;
                *(__nv_bfloat16*)(sm + SM_XL + rr * HPITCH_B + cc * 2) =
                    __float2bfloat16(vv[q] - __bfloat162float(hi));
            }
        }
    }
    __syncthreads();

    // ---- phase 3: per-type out heads
    const float ml = *max_logit;
    for (int t = 0; t < 3; t++) {
        if (tid < 32) logits_s[tid] = 0.f;
        __syncthreads();

        #pragma unroll
        for (int j = 0; j < 8; j++)
            #pragma unroll
            for (int q = 0; q < 4; q++) acc[j][q] = 0.f;

        for (int kt = 0; kt < 16; kt++) {
            uint32_t ah[4], al[4];
            const uint32_t addr = smb + SM_XH
                + (uint32_t)(wr * 16 + (lane & 15)) * HPITCH_B
                + ((uint32_t)(lane >> 4)) * 16 + (uint32_t)kt * 32;
            ldmatrix4(ah, addr);
            ldmatrix4(al, addr + (SM_XL - SM_XH));
            const int g = t * 16 + kt;
            #pragma unroll
            for (int j = 0; j < 8; j++) {
                const uint4 B = __ldg(&g_oWi[g * 1024 + ((wc * 8 + j) * 32 + lane)]);
                mma16816(acc[j], ah, B.x, B.y);
                mma16816(acc[j], ah, B.z, B.w);
                mma16816(acc[j], al, B.x, B.y);
            }
        }

        float p0 = 0.f, p1 = 0.f;
        #pragma unroll
        for (int j = 0; j < 8; j++) {
            const int c0 = wc * 64 + j * 8 + (lane & 3) * 2;
            const float bb0 = __ldg(&outb1[t * H + c0]);
            const float bb1 = __ldg(&outb1[t * H + c0 + 1]);
            const float w20 = __ldg(&outW2[t * H + c0]);
            const float w21 = __ldg(&outW2[t * H + c0 + 1]);
            p0 += lrelu(acc[j][0] + bb0) * w20 + lrelu(acc[j][1] + bb1) * w21;
            p1 += lrelu(acc[j][2] + bb0) * w20 + lrelu(acc[j][3] + bb1) * w21;
        }
        p0 += __shfl_xor_sync(0xffffffffu, p0, 1);
        p0 += __shfl_xor_sync(0xffffffffu, p0, 2);
        p1 += __shfl_xor_sync(0xffffffffu, p1, 1);
        p1 += __shfl_xor_sync(0xffffffffu, p1, 2);
        if ((lane & 3) == 0) {
            const int r0 = wr * 16 + (lane >> 2);
            atomicAdd(&logits_s[r0], p0);
            atomicAdd(&logits_s[r0 + 8], p1);
        }
        __syncthreads();
        if (tid < 32) {
            const int v = v0 + tid;
            if (vtypes[v] == t) {
                float l = logits_s[tid] + outb2[t];
                const int ci = min(g_alt_cnt[v], MAX_ALT);
                l *= conf[ci];
                out[v] = ml * tanhf(l / ml);
            }
        }
        __syncthreads();
    }
}

// ---------------- launch ----------------
extern "C" void kernel_launch(void* const* d_in, const int* in_sizes, int n_in,
                              void* d_out, int out_size)
{
    const float* reads  = (const float*)d_in[0];
    const float* info   = (const float*)d_in[1];
    const int*   refseg = (const int*)  d_in[2];
    const int*   altseg = (const int*)  d_in[3];
    const int*   vtypes = (const int*)  d_in[4];
    const float* phiW0  = (const float*)d_in[5];
    const float* phib0  = (const float*)d_in[6];
    const float* phiW1  = (const float*)d_in[7];
    const float* phib1  = (const float*)d_in[8];
    const float* omW0   = (const float*)d_in[9];
    const float* omb0   = (const float*)d_in[10];
    const float* rhoW0  = (const float*)d_in[11];
    const float* rhob0  = (const float*)d_in[12];
    const float* rhoW1  = (const float*)d_in[13];
    const float* rhob1  = (const float*)d_in[14];
    const float* outW1  = (const float*)d_in[15];
    const float* outb1  = (const float*)d_in[16];
    const float* outW2  = (const float*)d_in[17];
    const float* outb2  = (const float*)d_in[18];
    const float* conf   = (const float*)d_in[19];
    const float* maxl   = (const float*)d_in[20];
    float* out = (float*)d_out;

    cudaFuncSetAttribute(phi_mma_kernel,  cudaFuncAttributeMaxDynamicSharedMemorySize, PHI_SMEM_TOTAL);
    cudaFuncSetAttribute(head_mma_kernel, cudaFuncAttributeMaxDynamicSharedMemorySize, HEAD_SMEM_TOTAL);

    prelude_kernel<<<8704, 256>>>(phiW1, rhoW0, rhoW1, outW1);
    phi_mma_kernel<<<(NREF + NALT) / TILE_R, 256, PHI_SMEM_TOTAL>>>(
        reads, refseg, altseg, phiW0, phib0, phib1);
    build_X_kernel<<<V / 8, 256>>>(info, omW0, omb0);
    head_mma_kernel<<<V / 32, 256, HEAD_SMEM_TOTAL>>>(
        vtypes, rhob0, rhob1, outb1, outb2, outW2, conf, maxl, out);
}

// round 9
// speedup vs baseline: 3.0505x; 1.0228x over previous
#include <cuda_runtime.h>
#include <cuda_bf16.h>
#include <math.h>
#include <stdint.h>

#define V     8192
#define NREF  262144
#define NALT  131072
#define FREAD 11
#define FINFO 9
#define H     256
#define MAX_ALT 10

#define TILE_R 64

// ---------------- scratch ----------------
__device__ float g_ref_sums[V * H];
__device__ float g_alt_sums[V * H];
__device__ int   g_ref_cnt[V];
__device__ int   g_alt_cnt[V];
// weights, interleaved mma fragments: uint4 {hi_r0, hi_r1, lo_r0, lo_r1} per [kt][nt(32)][lane(32)]
__device__ __align__(16) uint4 g_W1i[16 * 1024];
__device__ __align__(16) uint4 g_r0i[48 * 1024];
__device__ __align__(16) uint4 g_r1i[16 * 1024];
__device__ __align__(16) uint4 g_oWi[48 * 1024];

// ---------------- helpers ----------------
__device__ __forceinline__ float lrelu(float x) { return x > 0.f ? x : 0.01f * x; }
__device__ __forceinline__ float sigmoidf_(float x) { return 1.f / (1.f + __expf(-x)); }

__device__ __forceinline__ uint32_t pack_bf16x2(__nv_bfloat16 lo16, __nv_bfloat16 hi16) {
    return ((uint32_t)__bfloat16_as_ushort(hi16) << 16) | (uint32_t)__bfloat16_as_ushort(lo16);
}

__device__ __forceinline__ void mma16816(float* c, const uint32_t* a, uint32_t b0, uint32_t b1) {
    asm volatile(
        "mma.sync.aligned.m16n8k16.row.col.f32.bf16.bf16.f32 "
        "{%0,%1,%2,%3}, {%4,%5,%6,%7}, {%8,%9}, {%0,%1,%2,%3};"
        : "+f"(c[0]), "+f"(c[1]), "+f"(c[2]), "+f"(c[3])
        : "r"(a[0]), "r"(a[1]), "r"(a[2]), "r"(a[3]), "r"(b0), "r"(b1));
}

__device__ __forceinline__ void ldmatrix4(uint32_t* r, uint32_t addr) {
    asm volatile("ldmatrix.sync.aligned.m8n8.x4.shared.b16 {%0,%1,%2,%3}, [%4];"
                 : "=r"(r[0]), "=r"(r[1]), "=r"(r[2]), "=r"(r[3]) : "r"(addr));
}

// ---------------- kernel 0: fused zero + all weight conversions ----------------
__global__ void prelude_kernel(const float* __restrict__ W1, const float* __restrict__ r0,
                               const float* __restrict__ r1, const float* __restrict__ oW) {
    const int b = blockIdx.x;
    const int tid = threadIdx.x;
    if (b < 8192) {
        const int idx = b * 256 + tid;
        g_ref_sums[idx] = 0.f;
        g_alt_sums[idx] = 0.f;
        if (idx < V) { g_ref_cnt[idx] = 0; g_alt_cnt[idx] = 0; }
        return;
    }
    int cb = b - 8192;
    const float* W;
    uint4* dst;
    if (cb < 64)       { W = W1; dst = g_W1i; }
    else if (cb < 256) { W = r0; dst = g_r0i; cb -= 64; }
    else if (cb < 320) { W = r1; dst = g_r1i; cb -= 256; }
    else               { W = oW; dst = g_oWi; cb -= 320; }
    const int idx = cb * 256 + tid;
    const int lane = idx & 31;
    const int nt   = (idx >> 5) & 31;
    const int kt   = idx >> 10;
    const int n = nt * 8 + (lane >> 2);
    const int kbase = kt * 16 + (lane & 3) * 2;
    uint32_t hv[2], lv[2];
    #pragma unroll
    for (int r = 0; r < 2; r++) {
        const int k = kbase + 8 * r;
        const float w0 = W[k * 256 + n];
        const float w1 = W[(k + 1) * 256 + n];
        __nv_bfloat16 h0 = __float2bfloat16(w0), h1 = __float2bfloat16(w1);
        __nv_bfloat16 l0 = __float2bfloat16(w0 - __bfloat162float(h0));
        __nv_bfloat16 l1 = __float2bfloat16(w1 - __bfloat162float(h1));
        hv[r] = pack_bf16x2(h0, h1);
        lv[r] = pack_bf16x2(l0, l1);
    }
    dst[idx] = make_uint4(hv[0], hv[1], lv[0], lv[1]);
}

// ---------------- kernel 1: fused phi MLP + segment reduce (64 rows, 2 blocks/SM) ----------------
#define HPITCH_B 528
#define SM_HSH   0
#define SM_HSL   (TILE_R * HPITCH_B)               // 33792
#define SM_XST   (2 * TILE_R * HPITCH_B)           // 67584
#define SM_SEGS  (SM_XST + FREAD * TILE_R * 4)     // 70400
#define PHI_SMEM_TOTAL (SM_SEGS + 512)             // 70912
#define YPITCH 257

__global__ __launch_bounds__(256, 2) void phi_mma_kernel(
    const float* __restrict__ reads,
    const int* __restrict__ ref_seg, const int* __restrict__ alt_seg,
    const float* __restrict__ W0, const float* __restrict__ b0,
    const float* __restrict__ b1)
{
    extern __shared__ char sm[];
    const uint32_t smb = (uint32_t)__cvta_generic_to_shared(sm);
    float* xsT  = (float*)(sm + SM_XST);
    int*   segs = (int*)(sm + SM_SEGS);
    float* ys   = (float*)sm;

    const int tid = threadIdx.x;
    const long base = (long)blockIdx.x * TILE_R;
    const bool is_alt = (base >= NREF);
    const int* seg_src = is_alt ? (alt_seg + (base - NREF)) : (ref_seg + base);

    for (int idx = tid; idx < TILE_R * FREAD; idx += 256) {
        int r = idx / FREAD, c = idx % FREAD;
        xsT[c * TILE_R + r] = reads[(base + r) * FREAD + c];
    }
    if (tid < TILE_R) segs[tid] = seg_src[tid];
    __syncthreads();

    if (tid < TILE_R) {
        int* cnt = is_alt ? g_alt_cnt : g_ref_cnt;
        atomicAdd(&cnt[segs[tid]], 1);
    }

    // stage 1: h = lrelu(x @ W0 + b0) -> bf16 hi/lo in smem (thread = column)
    {
        const int j = tid;
        float w[FREAD];
        #pragma unroll
        for (int k = 0; k < FREAD; k++) w[k] = W0[k * H + j];
        const float bb = b0[j];
        for (int r = 0; r < TILE_R; r += 4) {
            float a0 = bb, a1 = bb, a2 = bb, a3 = bb;
            #pragma unroll
            for (int k = 0; k < FREAD; k++) {
                const float4 a = *(const float4*)&xsT[k * TILE_R + r];
                a0 = fmaf(a.x, w[k], a0); a1 = fmaf(a.y, w[k], a1);
                a2 = fmaf(a.z, w[k], a2); a3 = fmaf(a.w, w[k], a3);
            }
            float hv[4] = {lrelu(a0), lrelu(a1), lrelu(a2), lrelu(a3)};
            #pragma unroll
            for (int q = 0; q < 4; q++) {
                __nv_bfloat16 hi = __float2bfloat16(hv[q]);
                __nv_bfloat16 lo = __float2bfloat16(hv[q] - __bfloat162float(hi));
                const int off = (r + q) * HPITCH_B + j * 2;
                *(__nv_bfloat16*)(sm + SM_HSH + off) = hi;
                *(__nv_bfloat16*)(sm + SM_HSL + off) = lo;
            }
        }
    }
    __syncthreads();

    // stage 2: D[64][256] = h @ W1, 3-term bf16 split
    const int wid = tid >> 5, lane = tid & 31;
    const int wr = wid >> 2, wc = wid & 3;
    const int rowbase = wr * 32;

    float acc[2][8][4];
    #pragma unroll
    for (int mt = 0; mt < 2; mt++)
        #pragma unroll
        for (int j = 0; j < 8; j++)
            #pragma unroll
            for (int q = 0; q < 4; q++) acc[mt][j][q] = 0.f;

    for (int kt = 0; kt < 16; kt++) {
        uint4 Bv[8];
        #pragma unroll
        for (int j = 0; j < 8; j++)
            Bv[j] = __ldg(&g_W1i[kt * 1024 + ((wc * 8 + j) * 32 + lane)]);
        uint32_t ah[2][4], al[2][4];
        #pragma unroll
        for (int mt = 0; mt < 2; mt++) {
            const uint32_t addr = smb + SM_HSH
                + (uint32_t)(rowbase + mt * 16 + (lane & 15)) * HPITCH_B
                + ((uint32_t)(lane >> 4)) * 16 + (uint32_t)kt * 32;
            ldmatrix4(ah[mt], addr);
            ldmatrix4(al[mt], addr + (SM_HSL - SM_HSH));
        }
        #pragma unroll
        for (int j = 0; j < 8; j++) {
            #pragma unroll
            for (int mt = 0; mt < 2; mt++) {
                mma16816(acc[mt][j], ah[mt], Bv[j].x, Bv[j].y);
                mma16816(acc[mt][j], ah[mt], Bv[j].z, Bv[j].w);
                mma16816(acc[mt][j], al[mt], Bv[j].x, Bv[j].y);
            }
        }
    }
    __syncthreads();

    // epilogue: bias + sigmoid -> ys[64][257]
    {
        const int colb = wc * 64 + 2 * (lane & 3);
        float bias0[8], bias1[8];
        #pragma unroll
        for (int j = 0; j < 8; j++) {
            bias0[j] = __ldg(&b1[colb + j * 8]);
            bias1[j] = __ldg(&b1[colb + j * 8 + 1]);
        }
        #pragma unroll
        for (int mt = 0; mt < 2; mt++) {
            const int row = rowbase + mt * 16 + (lane >> 2);
            #pragma unroll
            for (int j = 0; j < 8; j++) {
                const int col = colb + j * 8;
                ys[row * YPITCH + col]           = sigmoidf_(acc[mt][j][0] + bias0[j]);
                ys[row * YPITCH + col + 1]       = sigmoidf_(acc[mt][j][1] + bias1[j]);
                ys[(row + 8) * YPITCH + col]     = sigmoidf_(acc[mt][j][2] + bias0[j]);
                ys[(row + 8) * YPITCH + col + 1] = sigmoidf_(acc[mt][j][3] + bias1[j]);
            }
        }
    }
    __syncthreads();

    // sorted-run segment reduction: thread = column
    {
        float* sums = is_alt ? g_alt_sums : g_ref_sums;
        const int c = tid;
        int cur = segs[0];
        float a = 0.f;
        #pragma unroll 4
        for (int r = 0; r < TILE_R; r++) {
            int s = segs[r];
            if (s != cur) { atomicAdd(&sums[cur * H + c], a); a = 0.f; cur = s; }
            a += ys[r * YPITCH + c];
        }
        atomicAdd(&sums[cur * H + c], a);
    }
}

// ---------------- kernel 2: rho MLP + per-type heads (X computed in-kernel) ----------------
#define SM_XH    0
#define SM_XL    16896
#define SM_Z1H   33792
#define SM_Z1L   50688
#define SM_LOG   67584                    // 128 B (32 floats)
#define SM_OM    67712                    // 9 x 256 floats = 9216 B
#define SM_INFO  76928                    // 32 x 9 floats = 1152 B
#define SM_RCP   78080                    // 64 floats = 256 B
#define HEAD_SMEM_TOTAL 78336

__global__ __launch_bounds__(256, 2) void head_mma_kernel(
    const int* __restrict__ vtypes,
    const float* __restrict__ info,
    const float* __restrict__ omW0,  const float* __restrict__ omb0,
    const float* __restrict__ rhob0, const float* __restrict__ rhob1,
    const float* __restrict__ outb1, const float* __restrict__ outb2,
    const float* __restrict__ outW2,
    const float* __restrict__ conf,  const float* __restrict__ max_logit,
    float* __restrict__ out)
{
    extern __shared__ char sm[];
    const uint32_t smb = (uint32_t)__cvta_generic_to_shared(sm);
    float* logits_s = (float*)(sm + SM_LOG);
    float* om_s     = (float*)(sm + SM_OM);
    float* info_s   = (float*)(sm + SM_INFO);
    float* rcp_s    = (float*)(sm + SM_RCP);   // [0..31] ref, [32..63] alt

    const int tid = threadIdx.x;
    const int wid = tid >> 5, lane = tid & 31;
    const int wr = wid >> 2, wc = wid & 3;
    const int v0 = blockIdx.x * 32;

    // prologue: stage omW0, info rows, count reciprocals
    for (int i = tid; i < FINFO * H; i += 256) om_s[i] = omW0[i];
    for (int i = tid; i < 32 * FINFO; i += 256) info_s[i] = info[v0 * FINFO + i];
    if (tid < 32) {
        rcp_s[tid]      = 1.0f / (float)max(g_ref_cnt[v0 + tid], 1);
        rcp_s[tid + 32] = 1.0f / (float)max(g_alt_cnt[v0 + tid], 1);
    }
    __syncthreads();

    float acc[8][4];

    // ---- phase 1: z1 = lrelu(X @ rhoW0 + rhob0), K = 768 in 3 chunks of 256
    #pragma unroll
    for (int j = 0; j < 8; j++)
        #pragma unroll
        for (int q = 0; q < 4; q++) acc[j][q] = 0.f;

    for (int kb = 0; kb < 3; kb++) {
        // compute X chunk directly into smem (split bf16 hi/lo)
        if (kb < 2) {
            const float* sums = kb ? g_alt_sums : g_ref_sums;
            const float* rr   = rcp_s + kb * 32;
            for (int i = tid; i < 32 * H; i += 256) {
                const int c = i & 255, r = i >> 8;
                const float val = __ldg(&sums[(size_t)(v0 + r) * H + c]) * rr[r];
                __nv_bfloat16 hi = __float2bfloat16(val);
                *(__nv_bfloat16*)(sm + SM_XH + r * HPITCH_B + c * 2) = hi;
                *(__nv_bfloat16*)(sm + SM_XL + r * HPITCH_B + c * 2) =
                    __float2bfloat16(val - __bfloat162float(hi));
            }
        } else {
            for (int i = tid; i < 32 * H; i += 256) {
                const int c = i & 255, r = i >> 8;
                float z = __ldg(&omb0[c]);
                #pragma unroll
                for (int k = 0; k < FINFO; k++)
                    z = fmaf(info_s[r * FINFO + k], om_s[k * H + c], z);
                const float val = sigmoidf_(z);
                __nv_bfloat16 hi = __float2bfloat16(val);
                *(__nv_bfloat16*)(sm + SM_XH + r * HPITCH_B + c * 2) = hi;
                *(__nv_bfloat16*)(sm + SM_XL + r * HPITCH_B + c * 2) =
                    __float2bfloat16(val - __bfloat162float(hi));
            }
        }
        __syncthreads();
        for (int kt = 0; kt < 16; kt++) {
            const int g = kb * 16 + kt;
            uint4 Bv[8];
            #pragma unroll
            for (int j = 0; j < 8; j++)
                Bv[j] = __ldg(&g_r0i[g * 1024 + ((wc * 8 + j) * 32 + lane)]);
            uint32_t ah[4], al[4];
            const uint32_t addr = smb + SM_XH
                + (uint32_t)(wr * 16 + (lane & 15)) * HPITCH_B
                + ((uint32_t)(lane >> 4)) * 16 + (uint32_t)kt * 32;
            ldmatrix4(ah, addr);
            ldmatrix4(al, addr + (SM_XL - SM_XH));
            #pragma unroll
            for (int j = 0; j < 8; j++) {
                mma16816(acc[j], ah, Bv[j].x, Bv[j].y);
                mma16816(acc[j], ah, Bv[j].z, Bv[j].w);
                mma16816(acc[j], al, Bv[j].x, Bv[j].y);
            }
        }
        __syncthreads();
    }
    {
        const int r0 = wr * 16 + (lane >> 2);
        #pragma unroll
        for (int j = 0; j < 8; j++) {
            const int c0 = wc * 64 + j * 8 + (lane & 3) * 2;
            const float b0v = __ldg(&rhob0[c0]), b1v = __ldg(&rhob0[c0 + 1]);
            float vv[4] = {lrelu(acc[j][0] + b0v), lrelu(acc[j][1] + b1v),
                           lrelu(acc[j][2] + b0v), lrelu(acc[j][3] + b1v)};
            #pragma unroll
            for (int q = 0; q < 4; q++) {
                const int rr = (q < 2) ? r0 : r0 + 8;
                const int cc = c0 + (q & 1);
                __nv_bfloat16 hi = __float2bfloat16(vv[q]);
                *(__nv_bfloat16*)(sm + SM_Z1H + rr * HPITCH_B + cc * 2) = hi;
                *(__nv_bfloat16*)(sm + SM_Z1L + rr * HPITCH_B + cc * 2) =
                    __float2bfloat16(vv[q] - __bfloat162float(hi));
            }
        }
    }
    __syncthreads();

    // ---- phase 2: agg = z1 @ rhoW1 + rhob1 (K=256)
    #pragma unroll
    for (int j = 0; j < 8; j++)
        #pragma unroll
        for (int q = 0; q < 4; q++) acc[j][q] = 0.f;

    for (int kt = 0; kt < 16; kt++) {
        uint4 Bv[8];
        #pragma unroll
        for (int j = 0; j < 8; j++)
            Bv[j] = __ldg(&g_r1i[kt * 1024 + ((wc * 8 + j) * 32 + lane)]);
        uint32_t ah[4], al[4];
        const uint32_t addr = smb + SM_Z1H
            + (uint32_t)(wr * 16 + (lane & 15)) * HPITCH_B
            + ((uint32_t)(lane >> 4)) * 16 + (uint32_t)kt * 32;
        ldmatrix4(ah, addr);
        ldmatrix4(al, addr + (SM_Z1L - SM_Z1H));
        #pragma unroll
        for (int j = 0; j < 8; j++) {
            mma16816(acc[j], ah, Bv[j].x, Bv[j].y);
            mma16816(acc[j], ah, Bv[j].z, Bv[j].w);
            mma16816(acc[j], al, Bv[j].x, Bv[j].y);
        }
    }
    {
        const int r0 = wr * 16 + (lane >> 2);
        #pragma unroll
        for (int j = 0; j < 8; j++) {
            const int c0 = wc * 64 + j * 8 + (lane & 3) * 2;
            const float b0v = __ldg(&rhob1[c0]), b1v = __ldg(&rhob1[c0 + 1]);
            float vv[4] = {acc[j][0] + b0v, acc[j][1] + b1v,
                           acc[j][2] + b0v, acc[j][3] + b1v};
            #pragma unroll
            for (int q = 0; q < 4; q++) {
                const int rr = (q < 2) ? r0 : r0 + 8;
                const int cc = c0 + (q & 1);
                __nv_bfloat16 hi = __float2bfloat16(vv[q]);
                *(__nv_bfloat16*)(sm + SM_XH + rr * HPITCH_B + cc * 2) = hi;
                *(__nv_bfloat16*)(sm + SM_XL + rr * HPITCH_B + cc * 2) =
                    __float2bfloat16(vv[q] - __bfloat162float(hi));
            }
        }
    }
    __syncthreads();

    // ---- phase 3: per-type out heads
    const float ml = *max_logit;
    for (int t = 0; t < 3; t++) {
        if (tid < 32) logits_s[tid] = 0.f;
        __syncthreads();

        #pragma unroll
        for (int j = 0; j < 8; j++)
            #pragma unroll
            for (int q = 0; q < 4; q++) acc[j][q] = 0.f;

        for (int kt = 0; kt < 16; kt++) {
            const int g = t * 16 + kt;
            uint4 Bv[8];
            #pragma unroll
            for (int j = 0; j < 8; j++)
                Bv[j] = __ldg(&g_oWi[g * 1024 + ((wc * 8 + j) * 32 + lane)]);
            uint32_t ah[4], al[4];
            const uint32_t addr = smb + SM_XH
                + (uint32_t)(wr * 16 + (lane & 15)) * HPITCH_B
                + ((uint32_t)(lane >> 4)) * 16 + (uint32_t)kt * 32;
            ldmatrix4(ah, addr);
            ldmatrix4(al, addr + (SM_XL - SM_XH));
            #pragma unroll
            for (int j = 0; j < 8; j++) {
                mma16816(acc[j], ah, Bv[j].x, Bv[j].y);
                mma16816(acc[j], ah, Bv[j].z, Bv[j].w);
                mma16816(acc[j], al, Bv[j].x, Bv[j].y);
            }
        }

        float p0 = 0.f, p1 = 0.f;
        #pragma unroll
        for (int j = 0; j < 8; j++) {
            const int c0 = wc * 64 + j * 8 + (lane & 3) * 2;
            const float bb0 = __ldg(&outb1[t * H + c0]);
            const float bb1 = __ldg(&outb1[t * H + c0 + 1]);
            const float w20 = __ldg(&outW2[t * H + c0]);
            const float w21 = __ldg(&outW2[t * H + c0 + 1]);
            p0 += lrelu(acc[j][0] + bb0) * w20 + lrelu(acc[j][1] + bb1) * w21;
            p1 += lrelu(acc[j][2] + bb0) * w20 + lrelu(acc[j][3] + bb1) * w21;
        }
        p0 += __shfl_xor_sync(0xffffffffu, p0, 1);
        p0 += __shfl_xor_sync(0xffffffffu, p0, 2);
        p1 += __shfl_xor_sync(0xffffffffu, p1, 1);
        p1 += __shfl_xor_sync(0xffffffffu, p1, 2);
        if ((lane & 3) == 0) {
            const int r0 = wr * 16 + (lane >> 2);
            atomicAdd(&logits_s[r0], p0);
            atomicAdd(&logits_s[r0 + 8], p1);
        }
        __syncthreads();
        if (tid < 32) {
            const int v = v0 + tid;
            if (vtypes[v] == t) {
                float l = logits_s[tid] + outb2[t];
                const int ci = min(g_alt_cnt[v], MAX_ALT);
                l *= conf[ci];
                out[v] = ml * tanhf(l / ml);
            }
        }
        __syncthreads();
    }
}

// ---------------- launch ----------------
extern "C" void kernel_launch(void* const* d_in, const int* in_sizes, int n_in,
                              void* d_out, int out_size)
{
    const float* reads  = (const float*)d_in[0];
    const float* info   = (const float*)d_in[1];
    const int*   refseg = (const int*)  d_in[2];
    const int*   altseg = (const int*)  d_in[3];
    const int*   vtypes = (const int*)  d_in[4];
    const float* phiW0  = (const float*)d_in[5];
    const float* phib0  = (const float*)d_in[6];
    const float* phiW1  = (const float*)d_in[7];
    const float* phib1  = (const float*)d_in[8];
    const float* omW0   = (const float*)d_in[9];
    const float* omb0   = (const float*)d_in[10];
    const float* rhoW0  = (const float*)d_in[11];
    const float* rhob0  = (const float*)d_in[12];
    const float* rhoW1  = (const float*)d_in[13];
    const float* rhob1  = (const float*)d_in[14];
    const float* outW1  = (const float*)d_in[15];
    const float* outb1  = (const float*)d_in[16];
    const float* outW2  = (const float*)d_in[17];
    const float* outb2  = (const float*)d_in[18];
    const float* conf   = (const float*)d_in[19];
    const float* maxl   = (const float*)d_in[20];
    float* out = (float*)d_out;

    cudaFuncSetAttribute(phi_mma_kernel,  cudaFuncAttributeMaxDynamicSharedMemorySize, PHI_SMEM_TOTAL);
    cudaFuncSetAttribute(head_mma_kernel, cudaFuncAttributeMaxDynamicSharedMemorySize, HEAD_SMEM_TOTAL);

    prelude_kernel<<<8704, 256>>>(phiW1, rhoW0, rhoW1, outW1);
    phi_mma_kernel<<<(NREF + NALT) / TILE_R, 256, PHI_SMEM_TOTAL>>>(
        reads, refseg, altseg, phiW0, phib0, phib1);
    head_mma_kernel<<<V / 32, 256, HEAD_SMEM_TOTAL>>>(
        vtypes, info, omW0, omb0, rhob0, rhob1, outb1, outb2, outW2, conf, maxl, out);
}